// round 8
// baseline (speedup 1.0000x reference)
#include <cuda_runtime.h>
#include <math.h>
#include <stdint.h>

#define BDIM 4096
#define DDIM 1024
#define KSEL 1024
#define EPSV 1e-6f
#define MARGINV 0.5f
#define BIGV 1.0e6f

// ---------------- scratch (device globals; allocation-free) ----------------
__device__ float g_dist[(size_t)BDIM * BDIM];   // 64 MB
__device__ float g_distT[(size_t)BDIM * BDIM];  // 64 MB
__device__ float g_xr[(size_t)BDIM * DDIM];     // tf32-rounded X (16 MB)
__device__ float g_yr[(size_t)BDIM * DDIM];     // tf32-rounded Y (16 MB)
__device__ float g_nx[BDIM];
__device__ float g_ny[BDIM];
__device__ float g_sy[BDIM];
__device__ float g_rl[2 * BDIM];

// ---------------- helpers ----------------
__device__ __forceinline__ uint32_t smem_u32(const void* p) {
    uint32_t a;
    asm("{ .reg .u64 t; cvta.to.shared.u64 t, %1; cvt.u32.u64 %0, t; }" : "=r"(a) : "l"(p));
    return a;
}
__device__ __forceinline__ void cp16(void* dst, const void* src) {
    uint32_t d = smem_u32(dst);
    asm volatile("cp.async.cg.shared.global [%0], [%1], 16;" :: "r"(d), "l"(src));
}
#define CP_COMMIT() asm volatile("cp.async.commit_group;")
#define CP_WAIT1()  asm volatile("cp.async.wait_group 1;")

__device__ __forceinline__ float tf32_rna(float v) {
    uint32_t r;
    asm("cvt.rna.tf32.f32 %0, %1;" : "=r"(r) : "f"(v));
    return __uint_as_float(r);
}

__device__ __forceinline__ void mma_tf32(float* c, const uint32_t* a, const uint32_t* b) {
    asm volatile(
        "mma.sync.aligned.m16n8k8.row.col.f32.tf32.tf32.f32 "
        "{%0,%1,%2,%3}, {%4,%5,%6,%7}, {%8,%9}, {%0,%1,%2,%3};"
        : "+f"(c[0]), "+f"(c[1]), "+f"(c[2]), "+f"(c[3])
        : "r"(a[0]), "r"(a[1]), "r"(a[2]), "r"(a[3]), "r"(b[0]), "r"(b[1]));
}

// ---------------- GEMM config ----------------
#define BM 128
#define BN 128
#define BK 32
#define PITCH 36                          // floats; conflict-free frag reads
#define STAGE_FLOATS (2 * 128 * PITCH)    // A+B per stage = 9216 floats (36 KB)
#define GEMM_SMEM (2 * STAGE_FLOATS * 4)  // 73728 bytes

// ---------------------------------------------------------------------------
// Norms + tf32 pre-rounding (one float4 per thread)
// ---------------------------------------------------------------------------
__global__ void __launch_bounds__(256) norms_kernel(const float* __restrict__ X,
                                                    const float* __restrict__ Y) {
    __shared__ float s1[256], s2[256];
    const int row = blockIdx.x;
    const int isY = blockIdx.y;
    const int tid = threadIdx.x;
    const float4* p4 = (const float4*)((isY ? Y : X) + (size_t)row * DDIM);
    float4* pr4 = (float4*)((isY ? g_yr : g_xr) + (size_t)row * DDIM);

    float4 v = p4[tid];
    float4 r;
    r.x = tf32_rna(v.x); r.y = tf32_rna(v.y); r.z = tf32_rna(v.z); r.w = tf32_rna(v.w);
    pr4[tid] = r;

    float a, b = 0.0f;
    if (isY) {
        a = v.x * v.x + v.y * v.y + v.z * v.z + v.w * v.w;
        b = v.x + v.y + v.z + v.w;
    } else {
        float ex = v.x + EPSV, ey = v.y + EPSV, ez = v.z + EPSV, ew = v.w + EPSV;
        a = ex * ex + ey * ey + ez * ez + ew * ew;
    }
    s1[tid] = a; s2[tid] = b;
    __syncthreads();
    for (int off = 128; off; off >>= 1) {
        if (tid < off) { s1[tid] += s1[tid + off]; s2[tid] += s2[tid + off]; }
        __syncthreads();
    }
    if (tid == 0) {
        if (isY) { g_ny[row] = s1[0]; g_sy[row] = s2[0]; }
        else     { g_nx[row] = s1[0]; }
    }
}

// ---------------------------------------------------------------------------
// tf32 mma.sync GEMM + distance epilogue (writes dist AND distT).
// 128x128 tile/CTA, 4 warps (2x2), warp tile 64x64 (8 MAC/smem-byte),
// cp.async double buffer, 128 threads, 2 CTAs/SM.
// ---------------------------------------------------------------------------
__device__ __forceinline__ void issue_stage(float* sA, float* sB,
                                            const float* gA, const float* gB, int tid) {
#pragma unroll
    for (int i = 0; i < 8; i++) {
        const int idx = tid + i * 128;      // 0..1023
        const int r = idx >> 3;             // row 0..127
        const int c = (idx & 7) * 4;        // float col 0,4,..,28
        cp16(sA + r * PITCH + c, gA + (size_t)r * DDIM + c);
        cp16(sB + r * PITCH + c, gB + (size_t)r * DDIM + c);
    }
}

__global__ void __launch_bounds__(128, 2) gemm_mma_kernel() {
    extern __shared__ float smf[];
    const int tid = threadIdx.x;
    const int wid = tid >> 5;
    const int lane = tid & 31;
    const int wm = wid & 1;          // warp row 0..1  (64 rows each)
    const int wn = wid >> 1;         // warp col 0..1  (64 cols each)
    const int g = lane >> 2;         // 0..7
    const int t = lane & 3;          // 0..3
    const int bi = blockIdx.y * BM;
    const int bj = blockIdx.x * BN;

    const float* gA = g_xr + (size_t)bi * DDIM;
    const float* gB = g_yr + (size_t)bj * DDIM;

    float acc[4][8][4];
#pragma unroll
    for (int mi = 0; mi < 4; mi++)
#pragma unroll
        for (int ni = 0; ni < 8; ni++)
#pragma unroll
            for (int e = 0; e < 4; e++) acc[mi][ni][e] = 0.0f;

    // prologue: two stages in flight
    issue_stage(smf, smf + 128 * PITCH, gA, gB, tid);
    CP_COMMIT();
    issue_stage(smf + STAGE_FLOATS, smf + STAGE_FLOATS + 128 * PITCH,
                gA + BK, gB + BK, tid);
    CP_COMMIT();

    const int NCHUNK = DDIM / BK;    // 32
    for (int c = 0; c < NCHUNK; c++) {
        const int buf = c & 1;
        CP_WAIT1();
        __syncthreads();
        const uint32_t* sA = (const uint32_t*)(smf + buf * STAGE_FLOATS);
        const uint32_t* sB = sA + 128 * PITCH;

#pragma unroll
        for (int ks = 0; ks < 4; ks++) {
            const int k0 = ks * 8;
            uint32_t a[4][4], b[8][2];
#pragma unroll
            for (int mi = 0; mi < 4; mi++) {
                const int r0 = wm * 64 + mi * 16;
                a[mi][0] = sA[(r0 + g) * PITCH + k0 + t];
                a[mi][1] = sA[(r0 + g + 8) * PITCH + k0 + t];
                a[mi][2] = sA[(r0 + g) * PITCH + k0 + t + 4];
                a[mi][3] = sA[(r0 + g + 8) * PITCH + k0 + t + 4];
            }
#pragma unroll
            for (int ni = 0; ni < 8; ni++) {
                const int c0 = wn * 64 + ni * 8;
                b[ni][0] = sB[(c0 + g) * PITCH + k0 + t];
                b[ni][1] = sB[(c0 + g) * PITCH + k0 + t + 4];
            }
#pragma unroll
            for (int mi = 0; mi < 4; mi++)
#pragma unroll
                for (int ni = 0; ni < 8; ni++)
                    mma_tf32(acc[mi][ni], a[mi], b[ni]);
        }
        __syncthreads();
        if (c + 2 < NCHUNK)
            issue_stage(smf + buf * STAGE_FLOATS,
                        smf + buf * STAGE_FLOATS + 128 * PITCH,
                        gA + (c + 2) * BK, gB + (c + 2) * BK, tid);
        CP_COMMIT();
    }

    // -------- epilogue: regs -> smem tile (pitch 129) -> dist & distT --------
    __syncthreads();
    float* tile = smf;                       // 128 x 129
    float* nx_s = smf + 128 * 129;
    float* ny_s = nx_s + 128;
    float* sy_s = ny_s + 128;
    if (tid < 128) {
        nx_s[tid] = g_nx[bi + tid];
        ny_s[tid] = g_ny[bj + tid];
        sy_s[tid] = g_sy[bj + tid];
    }
    __syncthreads();

#pragma unroll
    for (int mi = 0; mi < 4; mi++) {
        const int r0 = wm * 64 + mi * 16 + g;
#pragma unroll
        for (int ni = 0; ni < 8; ni++) {
            const int c0 = wn * 64 + ni * 8 + 2 * t;
#pragma unroll
            for (int e = 0; e < 4; e++) {
                const int row = r0 + (e >> 1) * 8;
                const int col = c0 + (e & 1);
                float sq = nx_s[row] + ny_s[col] - 2.0f * acc[mi][ni][e]
                           - 2.0f * EPSV * sy_s[col];
                tile[row * 129 + col] = sqrtf(fmaxf(sq, 0.0f));
            }
        }
    }
    __syncthreads();

    // dist: coalesced float4 row writes
    for (int i = tid; i < 128 * 32; i += 128) {
        const int rr = i >> 5;
        const int c4 = (i & 31) << 2;
        float4 v;
        v.x = tile[rr * 129 + c4 + 0];
        v.y = tile[rr * 129 + c4 + 1];
        v.z = tile[rr * 129 + c4 + 2];
        v.w = tile[rr * 129 + c4 + 3];
        *(float4*)&g_dist[(size_t)(bi + rr) * BDIM + bj + c4] = v;
    }
    // distT: rr = tid, cc = iter; smem bank (tid+cc)%32 conflict-free, coalesced stores
#pragma unroll 4
    for (int cc = 0; cc < 128; cc++) {
        g_distT[(size_t)(bj + cc) * BDIM + bi + tid] = tile[tid * 129 + cc];
    }
}

// ---------------------------------------------------------------------------
// Per-row loss, exact K-th order statistic (register-resident, atomic-free
// pass-0 digit walk, reg-sourced histograms for passes 1-3). [as round 7]
// ---------------------------------------------------------------------------
__global__ void __launch_bounds__(256) select_kernel() {
    __shared__ unsigned hist[256];
    __shared__ float wf[8];
    __shared__ unsigned wu[8];
    __shared__ float wm8[8];
    __shared__ float s_t;
    __shared__ unsigned s_ctot;
    __shared__ float s_sall;
    __shared__ float s_min;
    __shared__ unsigned s_cd;
    __shared__ unsigned s_prefix, s_remk;

    const int row = blockIdx.x;
    const int tid = threadIdx.x;
    const int wid = tid >> 5;
    const int lane = tid & 31;
    const float* mat = blockIdx.y ? g_distT : g_dist;
    float* rl = g_rl + blockIdx.y * BDIM;
    const float4* rp4 = (const float4*)(mat + (size_t)row * BDIM);

    float4 rv[4];
#pragma unroll
    for (int q = 0; q < 4; q++) rv[q] = rp4[tid + q * 256];

    if (tid == 0) s_t = MARGINV + mat[(size_t)row * BDIM + row];

    {
        const int di = row >> 2;
        if ((di & 255) == tid) ((float*)&rv[di >> 8])[row & 3] = BIGV;
    }
    __syncthreads();
    const float t = s_t;

    unsigned c = 0; float s = 0.0f; float mn = BIGV;
#pragma unroll
    for (int q = 0; q < 4; q++) {
        const float* f = (const float*)&rv[q];
#pragma unroll
        for (int e = 0; e < 4; e++) {
            const float v = f[e];
            if (v < t) { c++; s += t - v; }
            mn = fminf(mn, v);
        }
    }
#pragma unroll
    for (int off = 16; off; off >>= 1) {
        c += __shfl_down_sync(0xFFFFFFFFu, c, off);
        s += __shfl_down_sync(0xFFFFFFFFu, s, off);
        mn = fminf(mn, __shfl_down_sync(0xFFFFFFFFu, mn, off));
    }
    if (lane == 0) { wu[wid] = c; wf[wid] = s; wm8[wid] = mn; }
    __syncthreads();
    if (tid == 0) {
        unsigned ct = 0; float st = 0.0f; float mt = BIGV;
#pragma unroll
        for (int w = 0; w < 8; w++) { ct += wu[w]; st += wf[w]; mt = fminf(mt, wm8[w]); }
        s_ctot = ct; s_sall = st; s_min = mt;
    }
    __syncthreads();

    if (s_ctot <= KSEL) {
        if (tid == 0) rl[row] = s_sall;
        return;
    }

    unsigned remk = KSEL;
    unsigned D = __float_as_uint(s_min) >> 24;
    for (;;) {
        unsigned cd = 0;
#pragma unroll
        for (int q = 0; q < 4; q++) {
            const float* f = (const float*)&rv[q];
#pragma unroll
            for (int e = 0; e < 4; e++)
                cd += ((__float_as_uint(f[e]) >> 24) == D);
        }
#pragma unroll
        for (int off = 16; off; off >>= 1)
            cd += __shfl_down_sync(0xFFFFFFFFu, cd, off);
        if (lane == 0) wu[wid] = cd;
        __syncthreads();
        if (tid == 0) {
            unsigned ct = 0;
#pragma unroll
            for (int w = 0; w < 8; w++) ct += wu[w];
            s_cd = ct;
        }
        __syncthreads();
        const unsigned cdtot = s_cd;
        __syncthreads();
        if (cdtot >= remk) break;
        remk -= cdtot;
        D++;
    }
    unsigned prefix = D << 24;

#pragma unroll
    for (int pass = 1; pass < 4; pass++) {
        const int shift = 24 - 8 * pass;
        hist[tid] = 0;
        __syncthreads();
        const unsigned pmask = 0xFFFFFFFFu << (shift + 8);
#pragma unroll
        for (int q = 0; q < 4; q++) {
            const float* f = (const float*)&rv[q];
#pragma unroll
            for (int e = 0; e < 4; e++) {
                const unsigned b = __float_as_uint(f[e]);
                if ((b & pmask) == prefix) atomicAdd(&hist[(b >> shift) & 255], 1u);
            }
        }
        __syncthreads();
        if (tid < 32) {
            unsigned loc[8]; unsigned lsum = 0;
#pragma unroll
            for (int j = 0; j < 8; j++) { loc[j] = hist[tid * 8 + j]; lsum += loc[j]; }
            unsigned incl = lsum;
#pragma unroll
            for (int off = 1; off < 32; off <<= 1) {
                unsigned y = __shfl_up_sync(0xFFFFFFFFu, incl, off);
                if (tid >= off) incl += y;
            }
            const unsigned excl = incl - lsum;
            if (excl < remk && incl >= remk) {
                unsigned cum = excl;
#pragma unroll
                for (int j = 0; j < 8; j++) {
                    if (cum + loc[j] >= remk) {
                        s_prefix = prefix | ((unsigned)(tid * 8 + j) << shift);
                        s_remk = remk - cum;
                        break;
                    }
                    cum += loc[j];
                }
            }
        }
        __syncthreads();
        prefix = s_prefix;
        remk = s_remk;
        __syncthreads();
    }
    const float theta = __uint_as_float(prefix);

    unsigned cl = 0; float sl = 0.0f;
#pragma unroll
    for (int q = 0; q < 4; q++) {
        const float* f = (const float*)&rv[q];
#pragma unroll
        for (int e = 0; e < 4; e++) {
            const float v = f[e];
            if (v < theta) { cl++; sl += v; }
        }
    }
#pragma unroll
    for (int off = 16; off; off >>= 1) {
        cl += __shfl_down_sync(0xFFFFFFFFu, cl, off);
        sl += __shfl_down_sync(0xFFFFFFFFu, sl, off);
    }
    if (lane == 0) { wu[wid] = cl; wf[wid] = sl; }
    __syncthreads();
    if (tid == 0) {
        unsigned ct = 0; float st = 0.0f;
#pragma unroll
        for (int w = 0; w < 8; w++) { ct += wu[w]; st += wf[w]; }
        rl[row] = (float)KSEL * t - st - (float)(KSEL - ct) * theta;
    }
}

// ---------------------------------------------------------------------------
__global__ void finalize_kernel(float* __restrict__ out) {
    __shared__ float sm[256];
    for (int which = 0; which < 2; which++) {
        float s = 0.0f;
        for (int i = threadIdx.x; i < BDIM; i += 256) s += g_rl[which * BDIM + i];
        sm[threadIdx.x] = s;
        __syncthreads();
        for (int off = 128; off; off >>= 1) {
            if (threadIdx.x < off) sm[threadIdx.x] += sm[threadIdx.x + off];
            __syncthreads();
        }
        if (threadIdx.x == 0) out[which] = sm[0] / ((float)BDIM * (float)KSEL);
        __syncthreads();
    }
}

// ---------------------------------------------------------------------------
extern "C" void kernel_launch(void* const* d_in, const int* in_sizes, int n_in,
                              void* d_out, int out_size) {
    const float* X = (const float*)d_in[0];
    const float* Y = (const float*)d_in[1];
    float* out = (float*)d_out;

    cudaFuncSetAttribute(gemm_mma_kernel, cudaFuncAttributeMaxDynamicSharedMemorySize,
                         GEMM_SMEM);

    norms_kernel<<<dim3(BDIM, 2), 256>>>(X, Y);
    gemm_mma_kernel<<<dim3(BDIM / BN, BDIM / BM), 128, GEMM_SMEM>>>();
    select_kernel<<<dim3(BDIM, 2), 256>>>();
    finalize_kernel<<<1, 256>>>(out);
}

// round 9
// speedup vs baseline: 1.0074x; 1.0074x over previous
#include <cuda_runtime.h>
#include <cuda_fp16.h>
#include <math.h>
#include <stdint.h>

#define BDIM 4096
#define DDIM 1024
#define KSEL 1024
#define EPSV 1e-6f
#define MARGINV 0.5f
#define BIGV 1.0e6f

// ---------------- scratch (device globals; allocation-free) ----------------
__device__ __half g_disth[(size_t)BDIM * BDIM];   // 32 MB
__device__ __half g_distTh[(size_t)BDIM * BDIM];  // 32 MB
__device__ float g_diag[BDIM];                    // fp32 diagonal (pos)
__device__ float g_xr[(size_t)BDIM * DDIM];       // tf32-rounded X (16 MB)
__device__ float g_yr[(size_t)BDIM * DDIM];       // tf32-rounded Y (16 MB)
__device__ float g_nx[BDIM];
__device__ float g_ny[BDIM];
__device__ float g_sy[BDIM];
__device__ float g_rl[2 * BDIM];

// ---------------- helpers ----------------
__device__ __forceinline__ uint32_t smem_u32(const void* p) {
    uint32_t a;
    asm("{ .reg .u64 t; cvta.to.shared.u64 t, %1; cvt.u32.u64 %0, t; }" : "=r"(a) : "l"(p));
    return a;
}
__device__ __forceinline__ void cp16(void* dst, const void* src) {
    uint32_t d = smem_u32(dst);
    asm volatile("cp.async.cg.shared.global [%0], [%1], 16;" :: "r"(d), "l"(src));
}
#define CP_COMMIT() asm volatile("cp.async.commit_group;")
#define CP_WAIT1()  asm volatile("cp.async.wait_group 1;")

__device__ __forceinline__ float tf32_rna(float v) {
    uint32_t r;
    asm("cvt.rna.tf32.f32 %0, %1;" : "=r"(r) : "f"(v));
    return __uint_as_float(r);
}

__device__ __forceinline__ void mma_tf32(float* c, const uint32_t* a, const uint32_t* b) {
    asm volatile(
        "mma.sync.aligned.m16n8k8.row.col.f32.tf32.tf32.f32 "
        "{%0,%1,%2,%3}, {%4,%5,%6,%7}, {%8,%9}, {%0,%1,%2,%3};"
        : "+f"(c[0]), "+f"(c[1]), "+f"(c[2]), "+f"(c[3])
        : "r"(a[0]), "r"(a[1]), "r"(a[2]), "r"(a[3]), "r"(b[0]), "r"(b[1]));
}

// ---------------- GEMM config (round-7 configuration) ----------------
#define BM 128
#define BN 128
#define BK 32
#define PITCH 36                          // floats; conflict-free frag reads
#define STAGE_FLOATS (2 * 128 * PITCH)    // A+B per stage = 9216 floats (36 KB)
#define GEMM_SMEM (2 * STAGE_FLOATS * 4)  // 73728 bytes

// ---------------------------------------------------------------------------
// Norms + tf32 pre-rounding (one float4 per thread)
// ---------------------------------------------------------------------------
__global__ void __launch_bounds__(256) norms_kernel(const float* __restrict__ X,
                                                    const float* __restrict__ Y) {
    __shared__ float s1[256], s2[256];
    const int row = blockIdx.x;
    const int isY = blockIdx.y;
    const int tid = threadIdx.x;
    const float4* p4 = (const float4*)((isY ? Y : X) + (size_t)row * DDIM);
    float4* pr4 = (float4*)((isY ? g_yr : g_xr) + (size_t)row * DDIM);

    float4 v = p4[tid];
    float4 r;
    r.x = tf32_rna(v.x); r.y = tf32_rna(v.y); r.z = tf32_rna(v.z); r.w = tf32_rna(v.w);
    pr4[tid] = r;

    float a, b = 0.0f;
    if (isY) {
        a = v.x * v.x + v.y * v.y + v.z * v.z + v.w * v.w;
        b = v.x + v.y + v.z + v.w;
    } else {
        float ex = v.x + EPSV, ey = v.y + EPSV, ez = v.z + EPSV, ew = v.w + EPSV;
        a = ex * ex + ey * ey + ez * ez + ew * ew;
    }
    s1[tid] = a; s2[tid] = b;
    __syncthreads();
    for (int off = 128; off; off >>= 1) {
        if (tid < off) { s1[tid] += s1[tid + off]; s2[tid] += s2[tid + off]; }
        __syncthreads();
    }
    if (tid == 0) {
        if (isY) { g_ny[row] = s1[0]; g_sy[row] = s2[0]; }
        else     { g_nx[row] = s1[0]; }
    }
}

// ---------------------------------------------------------------------------
// tf32 mma.sync GEMM + distance epilogue (fp16 dist & distT, fp32 diagonal).
// Mainloop identical to round 7 (best): 256 threads, 8 warps, 32x64 tiles.
// ---------------------------------------------------------------------------
__device__ __forceinline__ void issue_stage(float* sA, float* sB,
                                            const float* gA, const float* gB, int tid) {
#pragma unroll
    for (int i = 0; i < 4; i++) {
        const int idx = tid + i * 256;      // 0..1023
        const int r = idx >> 3;             // row 0..127
        const int c = (idx & 7) * 4;        // float col 0,4,..,28
        cp16(sA + r * PITCH + c, gA + (size_t)r * DDIM + c);
        cp16(sB + r * PITCH + c, gB + (size_t)r * DDIM + c);
    }
}

__global__ void __launch_bounds__(256, 2) gemm_mma_kernel() {
    extern __shared__ float smf[];
    const int tid = threadIdx.x;
    const int wid = tid >> 5;
    const int lane = tid & 31;
    const int wm = wid & 3;          // warp row 0..3  (32 rows each)
    const int wn = wid >> 2;         // warp col 0..1  (64 cols each)
    const int g = lane >> 2;
    const int t = lane & 3;
    const int bi = blockIdx.y * BM;
    const int bj = blockIdx.x * BN;

    const float* gA = g_xr + (size_t)bi * DDIM;
    const float* gB = g_yr + (size_t)bj * DDIM;

    float acc[2][8][4];
#pragma unroll
    for (int mi = 0; mi < 2; mi++)
#pragma unroll
        for (int ni = 0; ni < 8; ni++)
#pragma unroll
            for (int e = 0; e < 4; e++) acc[mi][ni][e] = 0.0f;

    issue_stage(smf, smf + 128 * PITCH, gA, gB, tid);
    CP_COMMIT();
    issue_stage(smf + STAGE_FLOATS, smf + STAGE_FLOATS + 128 * PITCH,
                gA + BK, gB + BK, tid);
    CP_COMMIT();

    const int NCHUNK = DDIM / BK;
    for (int c = 0; c < NCHUNK; c++) {
        const int buf = c & 1;
        CP_WAIT1();
        __syncthreads();
        const uint32_t* sA = (const uint32_t*)(smf + buf * STAGE_FLOATS);
        const uint32_t* sB = sA + 128 * PITCH;

#pragma unroll
        for (int ks = 0; ks < 4; ks++) {
            const int k0 = ks * 8;
            uint32_t a[2][4], b[8][2];
#pragma unroll
            for (int mi = 0; mi < 2; mi++) {
                const int r0 = wm * 32 + mi * 16;
                a[mi][0] = sA[(r0 + g) * PITCH + k0 + t];
                a[mi][1] = sA[(r0 + g + 8) * PITCH + k0 + t];
                a[mi][2] = sA[(r0 + g) * PITCH + k0 + t + 4];
                a[mi][3] = sA[(r0 + g + 8) * PITCH + k0 + t + 4];
            }
#pragma unroll
            for (int ni = 0; ni < 8; ni++) {
                const int c0 = wn * 64 + ni * 8;
                b[ni][0] = sB[(c0 + g) * PITCH + k0 + t];
                b[ni][1] = sB[(c0 + g) * PITCH + k0 + t + 4];
            }
#pragma unroll
            for (int mi = 0; mi < 2; mi++)
#pragma unroll
                for (int ni = 0; ni < 8; ni++)
                    mma_tf32(acc[mi][ni], a[mi], b[ni]);
        }
        __syncthreads();
        if (c + 2 < NCHUNK)
            issue_stage(smf + buf * STAGE_FLOATS,
                        smf + buf * STAGE_FLOATS + 128 * PITCH,
                        gA + (c + 2) * BK, gB + (c + 2) * BK, tid);
        CP_COMMIT();
    }

    // -------- epilogue: regs -> smem tile (pitch 129) -> fp16 dist & distT ---
    __syncthreads();
    float* tile = smf;                       // 128 x 129
    float* nx_s = smf + 128 * 129;
    float* ny_s = nx_s + 128;
    float* sy_s = ny_s + 128;
    if (tid < 128) {
        nx_s[tid] = g_nx[bi + tid];
        ny_s[tid] = g_ny[bj + tid];
        sy_s[tid] = g_sy[bj + tid];
    }
    __syncthreads();

#pragma unroll
    for (int mi = 0; mi < 2; mi++) {
        const int r0 = wm * 32 + mi * 16 + g;
#pragma unroll
        for (int ni = 0; ni < 8; ni++) {
            const int c0 = wn * 64 + ni * 8 + 2 * t;
#pragma unroll
            for (int e = 0; e < 4; e++) {
                const int row = r0 + (e >> 1) * 8;
                const int col = c0 + (e & 1);
                float sq = nx_s[row] + ny_s[col] - 2.0f * acc[mi][ni][e]
                           - 2.0f * EPSV * sy_s[col];
                tile[row * 129 + col] = sqrtf(fmaxf(sq, 0.0f));
            }
        }
    }
    __syncthreads();

    // fp32 diagonal (pos) for diagonal tiles
    if (blockIdx.x == blockIdx.y && tid < 128)
        g_diag[bi + tid] = tile[tid * 129 + tid];

    // dist: 4 halves per store (uint2), coalesced
    for (int i = tid; i < 128 * 32; i += 256) {
        const int rr = i >> 5;
        const int c4 = (i & 31) << 2;
        const float* tp = &tile[rr * 129 + c4];
        __half2 h0 = __floats2half2_rn(tp[0], tp[1]);
        __half2 h1 = __floats2half2_rn(tp[2], tp[3]);
        uint2 u = make_uint2(*(const uint32_t*)&h0, *(const uint32_t*)&h1);
        *(uint2*)&g_disth[(size_t)(bi + rr) * BDIM + bj + c4] = u;
    }
    // distT: conflict-free column reads, 2-byte coalesced stores
    for (int i = tid; i < 128 * 128; i += 256) {
        const int rr = i & 127;
        const int cc = i >> 7;
        g_distTh[(size_t)(bj + cc) * BDIM + bi + rr] = __float2half(tile[rr * 129 + cc]);
    }
}

// ---------------------------------------------------------------------------
// Per-row loss on fp16 distances. 16 halves/thread, register-resident.
// Order statistics on 16-bit half patterns (order-preserving for positives):
// atomic-free top-byte digit walk + ONE low-byte histogram pass.
// t (pos) read in fp32 from g_diag. Sums accumulated in fp32.
// grid (BDIM, 2): y=0 rows of dist (loss_xy), y=1 rows of distT (loss_yx).
// ---------------------------------------------------------------------------
__global__ void __launch_bounds__(256) select_kernel() {
    __shared__ unsigned hist[256];
    __shared__ float wf[8];
    __shared__ unsigned wu[8];
    __shared__ unsigned wmp[8];
    __shared__ float s_t;
    __shared__ unsigned s_ctot;
    __shared__ float s_sall;
    __shared__ unsigned s_minp;
    __shared__ unsigned s_cd;
    __shared__ unsigned s_theta, s_remk;

    const int row = blockIdx.x;
    const int tid = threadIdx.x;
    const int wid = tid >> 5;
    const int lane = tid & 31;
    const __half* mat = blockIdx.y ? g_distTh : g_disth;
    float* rl = g_rl + blockIdx.y * BDIM;
    const uint4* rp4 = (const uint4*)(mat + (size_t)row * BDIM);  // 8 halves/uint4

    // 16 halves per thread: patterns + fp32 copies
    unsigned short hs[16];
    float fv[16];
#pragma unroll
    for (int q = 0; q < 2; q++) {
        uint4 u = rp4[tid + q * 256];
        const unsigned w[4] = {u.x, u.y, u.z, u.w};
#pragma unroll
        for (int j = 0; j < 4; j++) {
            hs[q * 8 + 2 * j]     = (unsigned short)(w[j] & 0xFFFFu);
            hs[q * 8 + 2 * j + 1] = (unsigned short)(w[j] >> 16);
        }
#pragma unroll
        for (int j = 0; j < 8; j++)
            fv[q * 8 + j] = __half2float(__ushort_as_half(hs[q * 8 + j]));
    }

    if (tid == 0) s_t = MARGINV + g_diag[row];

    // patch diagonal in the owning thread's register copy
    {
        const int u4i = row >> 3;            // uint4 index of diagonal
        if ((u4i & 255) == tid) {
            const int slot = ((u4i >> 8) << 3) | (row & 7);
            hs[slot] = 0x7C00;               // +inf half
            fv[slot] = BIGV;
        }
    }
    __syncthreads();
    const float t = s_t;

    // ---- fused sweep: hinge count/sum vs t, and min pattern ----
    unsigned c = 0; float s = 0.0f; unsigned mnp = 0x7C00u;
#pragma unroll
    for (int j = 0; j < 16; j++) {
        const float v = fv[j];
        if (v < t) { c++; s += t - v; }
        mnp = min(mnp, (unsigned)hs[j]);
    }
#pragma unroll
    for (int off = 16; off; off >>= 1) {
        c += __shfl_down_sync(0xFFFFFFFFu, c, off);
        s += __shfl_down_sync(0xFFFFFFFFu, s, off);
        mnp = min(mnp, __shfl_down_sync(0xFFFFFFFFu, mnp, off));
    }
    if (lane == 0) { wu[wid] = c; wf[wid] = s; wmp[wid] = mnp; }
    __syncthreads();
    if (tid == 0) {
        unsigned ct = 0; float st = 0.0f; unsigned mt = 0x7C00u;
#pragma unroll
        for (int w = 0; w < 8; w++) { ct += wu[w]; st += wf[w]; mt = min(mt, wmp[w]); }
        s_ctot = ct; s_sall = st; s_minp = mt;
    }
    __syncthreads();

    if (s_ctot <= KSEL) {
        if (tid == 0) rl[row] = s_sall;
        return;
    }

    // ---- top-byte digit walk (atomic-free) ----
    unsigned remk = KSEL;
    unsigned D = s_minp >> 8;
    for (;;) {
        unsigned cd = 0;
#pragma unroll
        for (int j = 0; j < 16; j++)
            cd += (((unsigned)hs[j] >> 8) == D);
#pragma unroll
        for (int off = 16; off; off >>= 1)
            cd += __shfl_down_sync(0xFFFFFFFFu, cd, off);
        if (lane == 0) wu[wid] = cd;
        __syncthreads();
        if (tid == 0) {
            unsigned ct = 0;
#pragma unroll
            for (int w = 0; w < 8; w++) ct += wu[w];
            s_cd = ct;
        }
        __syncthreads();
        const unsigned cdtot = s_cd;
        __syncthreads();
        if (cdtot >= remk) break;
        remk -= cdtot;
        D++;
    }

    // ---- single low-byte histogram pass ----
    hist[tid] = 0;
    __syncthreads();
#pragma unroll
    for (int j = 0; j < 16; j++) {
        const unsigned b = hs[j];
        if ((b >> 8) == D) atomicAdd(&hist[b & 255u], 1u);
    }
    __syncthreads();
    if (tid < 32) {
        unsigned loc[8]; unsigned lsum = 0;
#pragma unroll
        for (int j = 0; j < 8; j++) { loc[j] = hist[tid * 8 + j]; lsum += loc[j]; }
        unsigned incl = lsum;
#pragma unroll
        for (int off = 1; off < 32; off <<= 1) {
            unsigned y = __shfl_up_sync(0xFFFFFFFFu, incl, off);
            if (tid >= off) incl += y;
        }
        const unsigned excl = incl - lsum;
        if (excl < remk && incl >= remk) {
            unsigned cum = excl;
#pragma unroll
            for (int j = 0; j < 8; j++) {
                if (cum + loc[j] >= remk) {
                    s_theta = (D << 8) | (unsigned)(tid * 8 + j);
                    break;
                }
                cum += loc[j];
            }
        }
    }
    __syncthreads();
    const unsigned theta_pat = s_theta;
    const float theta = __half2float(__ushort_as_half((unsigned short)theta_pat));

    // ---- final: sum/count strictly below theta ----
    unsigned cl = 0; float sl = 0.0f;
#pragma unroll
    for (int j = 0; j < 16; j++) {
        if ((unsigned)hs[j] < theta_pat) { cl++; sl += fv[j]; }
    }
#pragma unroll
    for (int off = 16; off; off >>= 1) {
        cl += __shfl_down_sync(0xFFFFFFFFu, cl, off);
        sl += __shfl_down_sync(0xFFFFFFFFu, sl, off);
    }
    if (lane == 0) { wu[wid] = cl; wf[wid] = sl; }
    __syncthreads();
    if (tid == 0) {
        unsigned ct = 0; float st = 0.0f;
#pragma unroll
        for (int w = 0; w < 8; w++) { ct += wu[w]; st += wf[w]; }
        rl[row] = (float)KSEL * t - st - (float)(KSEL - ct) * theta;
    }
}

// ---------------------------------------------------------------------------
__global__ void finalize_kernel(float* __restrict__ out) {
    __shared__ float sm[256];
    for (int which = 0; which < 2; which++) {
        float s = 0.0f;
        for (int i = threadIdx.x; i < BDIM; i += 256) s += g_rl[which * BDIM + i];
        sm[threadIdx.x] = s;
        __syncthreads();
        for (int off = 128; off; off >>= 1) {
            if (threadIdx.x < off) sm[threadIdx.x] += sm[threadIdx.x + off];
            __syncthreads();
        }
        if (threadIdx.x == 0) out[which] = sm[0] / ((float)BDIM * (float)KSEL);
        __syncthreads();
    }
}

// ---------------------------------------------------------------------------
extern "C" void kernel_launch(void* const* d_in, const int* in_sizes, int n_in,
                              void* d_out, int out_size) {
    const float* X = (const float*)d_in[0];
    const float* Y = (const float*)d_in[1];
    float* out = (float*)d_out;

    cudaFuncSetAttribute(gemm_mma_kernel, cudaFuncAttributeMaxDynamicSharedMemorySize,
                         GEMM_SMEM);

    norms_kernel<<<dim3(BDIM, 2), 256>>>(X, Y);
    gemm_mma_kernel<<<dim3(BDIM / BN, BDIM / BM), 256, GEMM_SMEM>>>();
    select_kernel<<<dim3(BDIM, 2), 256>>>();
    finalize_kernel<<<1, 256>>>(out);
}

// round 10
// speedup vs baseline: 1.0118x; 1.0044x over previous
#include <cuda_runtime.h>
#include <cuda_fp16.h>
#include <math.h>
#include <stdint.h>

#define BDIM 4096
#define DDIM 1024
#define KSEL 1024
#define EPSV 1e-6f
#define MARGINV 0.5f
#define BIGV 1.0e6f

// ---------------- scratch (device globals; allocation-free) ----------------
__device__ __half g_disth[(size_t)BDIM * BDIM];   // 32 MB
__device__ __half g_distTh[(size_t)BDIM * BDIM];  // 32 MB
__device__ float g_diag[BDIM];                    // fp32 diagonal (pos)
__device__ float g_xr[(size_t)BDIM * DDIM];       // tf32-rounded X (16 MB)
__device__ float g_yr[(size_t)BDIM * DDIM];       // tf32-rounded Y (16 MB)
__device__ float g_nx[BDIM];
__device__ float g_ny[BDIM];
__device__ float g_sy[BDIM];
__device__ float g_rl[2 * BDIM];

// ---------------- helpers ----------------
__device__ __forceinline__ uint32_t smem_u32(const void* p) {
    uint32_t a;
    asm("{ .reg .u64 t; cvta.to.shared.u64 t, %1; cvt.u32.u64 %0, t; }" : "=r"(a) : "l"(p));
    return a;
}
__device__ __forceinline__ void cp16(void* dst, const void* src) {
    uint32_t d = smem_u32(dst);
    asm volatile("cp.async.cg.shared.global [%0], [%1], 16;" :: "r"(d), "l"(src));
}
#define CP_COMMIT() asm volatile("cp.async.commit_group;")
#define CP_WAIT1()  asm volatile("cp.async.wait_group 1;")

__device__ __forceinline__ float tf32_rna(float v) {
    uint32_t r;
    asm("cvt.rna.tf32.f32 %0, %1;" : "=r"(r) : "f"(v));
    return __uint_as_float(r);
}

__device__ __forceinline__ void mma_tf32(float* c, const uint32_t* a, const uint32_t* b) {
    asm volatile(
        "mma.sync.aligned.m16n8k8.row.col.f32.tf32.tf32.f32 "
        "{%0,%1,%2,%3}, {%4,%5,%6,%7}, {%8,%9}, {%0,%1,%2,%3};"
        : "+f"(c[0]), "+f"(c[1]), "+f"(c[2]), "+f"(c[3])
        : "r"(a[0]), "r"(a[1]), "r"(a[2]), "r"(a[3]), "r"(b[0]), "r"(b[1]));
}

// ---------------- GEMM config ----------------
#define BM 128
#define BN 128
#define BK 32
#define PITCH 36                          // floats; conflict-free frag reads
#define STAGE_FLOATS (2 * 128 * PITCH)    // A+B per stage = 9216 floats (36 KB)
#define NSTAGE 3
#define GEMM_SMEM (NSTAGE * STAGE_FLOATS * 4)   // 110592 bytes

// ---------------------------------------------------------------------------
// Norms + tf32 pre-rounding (one float4 per thread)
// ---------------------------------------------------------------------------
__global__ void __launch_bounds__(256) norms_kernel(const float* __restrict__ X,
                                                    const float* __restrict__ Y) {
    __shared__ float s1[256], s2[256];
    const int row = blockIdx.x;
    const int isY = blockIdx.y;
    const int tid = threadIdx.x;
    const float4* p4 = (const float4*)((isY ? Y : X) + (size_t)row * DDIM);
    float4* pr4 = (float4*)((isY ? g_yr : g_xr) + (size_t)row * DDIM);

    float4 v = p4[tid];
    float4 r;
    r.x = tf32_rna(v.x); r.y = tf32_rna(v.y); r.z = tf32_rna(v.z); r.w = tf32_rna(v.w);
    pr4[tid] = r;

    float a, b = 0.0f;
    if (isY) {
        a = v.x * v.x + v.y * v.y + v.z * v.z + v.w * v.w;
        b = v.x + v.y + v.z + v.w;
    } else {
        float ex = v.x + EPSV, ey = v.y + EPSV, ez = v.z + EPSV, ew = v.w + EPSV;
        a = ex * ex + ey * ey + ez * ez + ew * ew;
    }
    s1[tid] = a; s2[tid] = b;
    __syncthreads();
    for (int off = 128; off; off >>= 1) {
        if (tid < off) { s1[tid] += s1[tid + off]; s2[tid] += s2[tid + off]; }
        __syncthreads();
    }
    if (tid == 0) {
        if (isY) { g_ny[row] = s1[0]; g_sy[row] = s2[0]; }
        else     { g_nx[row] = s1[0]; }
    }
}

// ---------------------------------------------------------------------------
// tf32 mma.sync GEMM + distance epilogue (fp16 dist & distT, fp32 diagonal).
// 128x128 tile/CTA, 8 warps (4x2), warp tile 32x64.
// 3-stage cp.async pipeline with ONE barrier per chunk: chunk c+2 is issued
// into buffer (c+2)%3 (freed by chunk c-1's consumption, fenced by this
// iteration's barrier) BEFORE computing chunk c.
// ---------------------------------------------------------------------------
__device__ __forceinline__ void issue_stage(float* sA, float* sB,
                                            const float* gA, const float* gB, int tid) {
#pragma unroll
    for (int i = 0; i < 4; i++) {
        const int idx = tid + i * 256;      // 0..1023
        const int r = idx >> 3;             // row 0..127
        const int c = (idx & 7) * 4;        // float col 0,4,..,28
        cp16(sA + r * PITCH + c, gA + (size_t)r * DDIM + c);
        cp16(sB + r * PITCH + c, gB + (size_t)r * DDIM + c);
    }
}

__global__ void __launch_bounds__(256, 2) gemm_mma_kernel() {
    extern __shared__ float smf[];
    const int tid = threadIdx.x;
    const int wid = tid >> 5;
    const int lane = tid & 31;
    const int wm = wid & 3;          // warp row 0..3  (32 rows each)
    const int wn = wid >> 2;         // warp col 0..1  (64 cols each)
    const int g = lane >> 2;
    const int t = lane & 3;
    const int bi = blockIdx.y * BM;
    const int bj = blockIdx.x * BN;

    const float* gA = g_xr + (size_t)bi * DDIM;
    const float* gB = g_yr + (size_t)bj * DDIM;

    float acc[2][8][4];
#pragma unroll
    for (int mi = 0; mi < 2; mi++)
#pragma unroll
        for (int ni = 0; ni < 8; ni++)
#pragma unroll
            for (int e = 0; e < 4; e++) acc[mi][ni][e] = 0.0f;

    // prologue: two chunks in flight
    issue_stage(smf, smf + 128 * PITCH, gA, gB, tid);
    CP_COMMIT();
    issue_stage(smf + STAGE_FLOATS, smf + STAGE_FLOATS + 128 * PITCH,
                gA + BK, gB + BK, tid);
    CP_COMMIT();

    const int NCHUNK = DDIM / BK;    // 32
    for (int c = 0; c < NCHUNK; c++) {
        CP_WAIT1();                  // chunk c arrived
        __syncthreads();             // visible to all; buf (c+2)%3 free

        // issue chunk c+2 BEFORE compute (overlaps LDG with MMA)
        if (c + 2 < NCHUNK) {
            float* nb = smf + ((c + 2) % NSTAGE) * STAGE_FLOATS;
            issue_stage(nb, nb + 128 * PITCH,
                        gA + (c + 2) * BK, gB + (c + 2) * BK, tid);
        }
        CP_COMMIT();                 // commit (possibly empty) group

        const uint32_t* sA = (const uint32_t*)(smf + (c % NSTAGE) * STAGE_FLOATS);
        const uint32_t* sB = sA + 128 * PITCH;

#pragma unroll
        for (int ks = 0; ks < 4; ks++) {
            const int k0 = ks * 8;
            uint32_t a[2][4], b[8][2];
#pragma unroll
            for (int mi = 0; mi < 2; mi++) {
                const int r0 = wm * 32 + mi * 16;
                a[mi][0] = sA[(r0 + g) * PITCH + k0 + t];
                a[mi][1] = sA[(r0 + g + 8) * PITCH + k0 + t];
                a[mi][2] = sA[(r0 + g) * PITCH + k0 + t + 4];
                a[mi][3] = sA[(r0 + g + 8) * PITCH + k0 + t + 4];
            }
#pragma unroll
            for (int ni = 0; ni < 8; ni++) {
                const int c0 = wn * 64 + ni * 8;
                b[ni][0] = sB[(c0 + g) * PITCH + k0 + t];
                b[ni][1] = sB[(c0 + g) * PITCH + k0 + t + 4];
            }
#pragma unroll
            for (int mi = 0; mi < 2; mi++)
#pragma unroll
                for (int ni = 0; ni < 8; ni++)
                    mma_tf32(acc[mi][ni], a[mi], b[ni]);
        }
    }

    // -------- epilogue: regs -> smem tile (pitch 129) -> fp16 dist & distT ---
    __syncthreads();
    float* tile = smf;                       // 128 x 129
    float* nx_s = smf + 128 * 129;
    float* ny_s = nx_s + 128;
    float* sy_s = ny_s + 128;
    if (tid < 128) {
        nx_s[tid] = g_nx[bi + tid];
        ny_s[tid] = g_ny[bj + tid];
        sy_s[tid] = g_sy[bj + tid];
    }
    __syncthreads();

#pragma unroll
    for (int mi = 0; mi < 2; mi++) {
        const int r0 = wm * 32 + mi * 16 + g;
#pragma unroll
        for (int ni = 0; ni < 8; ni++) {
            const int c0 = wn * 64 + ni * 8 + 2 * t;
#pragma unroll
            for (int e = 0; e < 4; e++) {
                const int row = r0 + (e >> 1) * 8;
                const int col = c0 + (e & 1);
                float sq = nx_s[row] + ny_s[col] - 2.0f * acc[mi][ni][e]
                           - 2.0f * EPSV * sy_s[col];
                tile[row * 129 + col] = sqrtf(fmaxf(sq, 0.0f));
            }
        }
    }
    __syncthreads();

    // fp32 diagonal (pos) for diagonal tiles
    if (blockIdx.x == blockIdx.y && tid < 128)
        g_diag[bi + tid] = tile[tid * 129 + tid];

    // dist: 4 halves per store (uint2), coalesced
    for (int i = tid; i < 128 * 32; i += 256) {
        const int rr = i >> 5;
        const int c4 = (i & 31) << 2;
        const float* tp = &tile[rr * 129 + c4];
        __half2 h0 = __floats2half2_rn(tp[0], tp[1]);
        __half2 h1 = __floats2half2_rn(tp[2], tp[3]);
        uint2 u = make_uint2(*(const uint32_t*)&h0, *(const uint32_t*)&h1);
        *(uint2*)&g_disth[(size_t)(bi + rr) * BDIM + bj + c4] = u;
    }
    // distT: conflict-free column reads, 2-byte coalesced stores
    for (int i = tid; i < 128 * 128; i += 256) {
        const int rr = i & 127;
        const int cc = i >> 7;
        g_distTh[(size_t)(bj + cc) * BDIM + bi + rr] = __float2half(tile[rr * 129 + cc]);
    }
}

// ---------------------------------------------------------------------------
// Per-row loss on fp16 distances (register-resident 16-bit radix select).
// [unchanged from round 9]
// ---------------------------------------------------------------------------
__global__ void __launch_bounds__(256) select_kernel() {
    __shared__ unsigned hist[256];
    __shared__ float wf[8];
    __shared__ unsigned wu[8];
    __shared__ unsigned wmp[8];
    __shared__ float s_t;
    __shared__ unsigned s_ctot;
    __shared__ float s_sall;
    __shared__ unsigned s_minp;
    __shared__ unsigned s_cd;
    __shared__ unsigned s_theta;

    const int row = blockIdx.x;
    const int tid = threadIdx.x;
    const int wid = tid >> 5;
    const int lane = tid & 31;
    const __half* mat = blockIdx.y ? g_distTh : g_disth;
    float* rl = g_rl + blockIdx.y * BDIM;
    const uint4* rp4 = (const uint4*)(mat + (size_t)row * BDIM);

    unsigned short hs[16];
    float fv[16];
#pragma unroll
    for (int q = 0; q < 2; q++) {
        uint4 u = rp4[tid + q * 256];
        const unsigned w[4] = {u.x, u.y, u.z, u.w};
#pragma unroll
        for (int j = 0; j < 4; j++) {
            hs[q * 8 + 2 * j]     = (unsigned short)(w[j] & 0xFFFFu);
            hs[q * 8 + 2 * j + 1] = (unsigned short)(w[j] >> 16);
        }
#pragma unroll
        for (int j = 0; j < 8; j++)
            fv[q * 8 + j] = __half2float(__ushort_as_half(hs[q * 8 + j]));
    }

    if (tid == 0) s_t = MARGINV + g_diag[row];

    {
        const int u4i = row >> 3;
        if ((u4i & 255) == tid) {
            const int slot = ((u4i >> 8) << 3) | (row & 7);
            hs[slot] = 0x7C00;
            fv[slot] = BIGV;
        }
    }
    __syncthreads();
    const float t = s_t;

    unsigned c = 0; float s = 0.0f; unsigned mnp = 0x7C00u;
#pragma unroll
    for (int j = 0; j < 16; j++) {
        const float v = fv[j];
        if (v < t) { c++; s += t - v; }
        mnp = min(mnp, (unsigned)hs[j]);
    }
#pragma unroll
    for (int off = 16; off; off >>= 1) {
        c += __shfl_down_sync(0xFFFFFFFFu, c, off);
        s += __shfl_down_sync(0xFFFFFFFFu, s, off);
        mnp = min(mnp, __shfl_down_sync(0xFFFFFFFFu, mnp, off));
    }
    if (lane == 0) { wu[wid] = c; wf[wid] = s; wmp[wid] = mnp; }
    __syncthreads();
    if (tid == 0) {
        unsigned ct = 0; float st = 0.0f; unsigned mt = 0x7C00u;
#pragma unroll
        for (int w = 0; w < 8; w++) { ct += wu[w]; st += wf[w]; mt = min(mt, wmp[w]); }
        s_ctot = ct; s_sall = st; s_minp = mt;
    }
    __syncthreads();

    if (s_ctot <= KSEL) {
        if (tid == 0) rl[row] = s_sall;
        return;
    }

    unsigned remk = KSEL;
    unsigned D = s_minp >> 8;
    for (;;) {
        unsigned cd = 0;
#pragma unroll
        for (int j = 0; j < 16; j++)
            cd += (((unsigned)hs[j] >> 8) == D);
#pragma unroll
        for (int off = 16; off; off >>= 1)
            cd += __shfl_down_sync(0xFFFFFFFFu, cd, off);
        if (lane == 0) wu[wid] = cd;
        __syncthreads();
        if (tid == 0) {
            unsigned ct = 0;
#pragma unroll
            for (int w = 0; w < 8; w++) ct += wu[w];
            s_cd = ct;
        }
        __syncthreads();
        const unsigned cdtot = s_cd;
        __syncthreads();
        if (cdtot >= remk) break;
        remk -= cdtot;
        D++;
    }

    hist[tid] = 0;
    __syncthreads();
#pragma unroll
    for (int j = 0; j < 16; j++) {
        const unsigned b = hs[j];
        if ((b >> 8) == D) atomicAdd(&hist[b & 255u], 1u);
    }
    __syncthreads();
    if (tid < 32) {
        unsigned loc[8]; unsigned lsum = 0;
#pragma unroll
        for (int j = 0; j < 8; j++) { loc[j] = hist[tid * 8 + j]; lsum += loc[j]; }
        unsigned incl = lsum;
#pragma unroll
        for (int off = 1; off < 32; off <<= 1) {
            unsigned y = __shfl_up_sync(0xFFFFFFFFu, incl, off);
            if (tid >= off) incl += y;
        }
        const unsigned excl = incl - lsum;
        if (excl < remk && incl >= remk) {
            unsigned cum = excl;
#pragma unroll
            for (int j = 0; j < 8; j++) {
                if (cum + loc[j] >= remk) {
                    s_theta = (D << 8) | (unsigned)(tid * 8 + j);
                    break;
                }
                cum += loc[j];
            }
        }
    }
    __syncthreads();
    const unsigned theta_pat = s_theta;
    const float theta = __half2float(__ushort_as_half((unsigned short)theta_pat));

    unsigned cl = 0; float sl = 0.0f;
#pragma unroll
    for (int j = 0; j < 16; j++) {
        if ((unsigned)hs[j] < theta_pat) { cl++; sl += fv[j]; }
    }
#pragma unroll
    for (int off = 16; off; off >>= 1) {
        cl += __shfl_down_sync(0xFFFFFFFFu, cl, off);
        sl += __shfl_down_sync(0xFFFFFFFFu, sl, off);
    }
    if (lane == 0) { wu[wid] = cl; wf[wid] = sl; }
    __syncthreads();
    if (tid == 0) {
        unsigned ct = 0; float st = 0.0f;
#pragma unroll
        for (int w = 0; w < 8; w++) { ct += wu[w]; st += wf[w]; }
        rl[row] = (float)KSEL * t - st - (float)(KSEL - ct) * theta;
    }
}

// ---------------------------------------------------------------------------
__global__ void finalize_kernel(float* __restrict__ out) {
    __shared__ float sm[256];
    for (int which = 0; which < 2; which++) {
        float s = 0.0f;
        for (int i = threadIdx.x; i < BDIM; i += 256) s += g_rl[which * BDIM + i];
        sm[threadIdx.x] = s;
        __syncthreads();
        for (int off = 128; off; off >>= 1) {
            if (threadIdx.x < off) sm[threadIdx.x] += sm[threadIdx.x + off];
            __syncthreads();
        }
        if (threadIdx.x == 0) out[which] = sm[0] / ((float)BDIM * (float)KSEL);
        __syncthreads();
    }
}

// ---------------------------------------------------------------------------
extern "C" void kernel_launch(void* const* d_in, const int* in_sizes, int n_in,
                              void* d_out, int out_size) {
    const float* X = (const float*)d_in[0];
    const float* Y = (const float*)d_in[1];
    float* out = (float*)d_out;

    cudaFuncSetAttribute(gemm_mma_kernel, cudaFuncAttributeMaxDynamicSharedMemorySize,
                         GEMM_SMEM);

    norms_kernel<<<dim3(BDIM, 2), 256>>>(X, Y);
    gemm_mma_kernel<<<dim3(BDIM / BN, BDIM / BM), 256, GEMM_SMEM>>>();
    select_kernel<<<dim3(BDIM, 2), 256>>>();
    finalize_kernel<<<1, 256>>>(out);
}

// round 11
// speedup vs baseline: 1.5030x; 1.4855x over previous
#include <cuda_runtime.h>
#include <cuda_fp16.h>
#include <math.h>
#include <stdint.h>

#define BDIM 4096
#define DDIM 1024
#define KSEL 1024
#define EPSV 1e-6f
#define MARGINV 0.5f
#define BIGV 1.0e6f

// ---------------- scratch (device globals; allocation-free) ----------------
__device__ __half g_disth[(size_t)BDIM * BDIM];   // 32 MB
__device__ __half g_distTh[(size_t)BDIM * BDIM];  // 32 MB
__device__ float g_diag[BDIM];                    // fp32 diagonal (pos)
__device__ __half g_xh[(size_t)BDIM * DDIM];      // fp16-rounded X (8 MB)
__device__ __half g_yh[(size_t)BDIM * DDIM];      // fp16-rounded Y (8 MB)
__device__ float g_nx[BDIM];
__device__ float g_ny[BDIM];
__device__ float g_sy[BDIM];
__device__ float g_rl[2 * BDIM];

// ---------------- helpers ----------------
__device__ __forceinline__ uint32_t smem_u32(const void* p) {
    uint32_t a;
    asm("{ .reg .u64 t; cvta.to.shared.u64 t, %1; cvt.u32.u64 %0, t; }" : "=r"(a) : "l"(p));
    return a;
}
__device__ __forceinline__ void cp16(void* dst, const void* src) {
    uint32_t d = smem_u32(dst);
    asm volatile("cp.async.cg.shared.global [%0], [%1], 16;" :: "r"(d), "l"(src));
}
#define CP_COMMIT() asm volatile("cp.async.commit_group;")
#define CP_WAIT1()  asm volatile("cp.async.wait_group 1;")

// fp16 mma: D(16x8,f32) += A(16x16,f16) * B(16x8,f16)
__device__ __forceinline__ void mma_f16(float* c, const uint32_t* a, const uint32_t* b) {
    asm volatile(
        "mma.sync.aligned.m16n8k16.row.col.f32.f16.f16.f32 "
        "{%0,%1,%2,%3}, {%4,%5,%6,%7}, {%8,%9}, {%0,%1,%2,%3};"
        : "+f"(c[0]), "+f"(c[1]), "+f"(c[2]), "+f"(c[3])
        : "r"(a[0]), "r"(a[1]), "r"(a[2]), "r"(a[3]), "r"(b[0]), "r"(b[1]));
}

// ---------------- GEMM config ----------------
#define BM 128
#define BN 128
#define BK 64                              // halves per k-chunk (128 B rows)
#define PITCHH 72                          // halves per smem row (144 B) — conflict-free
#define PITCHW 36                          // words per smem row
#define STAGE_HALves 0
#define STAGE_BYTES (2 * 128 * PITCHH * 2) // A+B per stage = 36864 B
#define NSTAGE 3
#define GEMM_SMEM (NSTAGE * STAGE_BYTES)   // 110592 B

// ---------------------------------------------------------------------------
// Norms + fp16 pre-rounding (one float4 per thread):
//   nx[i]=||x_i+eps||^2, ny[j]=||y_j||^2, sy[j]=sum(y_j) in fp32;
//   g_xh = half(X), g_yh = half(Y)
// ---------------------------------------------------------------------------
__global__ void __launch_bounds__(256) norms_kernel(const float* __restrict__ X,
                                                    const float* __restrict__ Y) {
    __shared__ float s1[256], s2[256];
    const int row = blockIdx.x;
    const int isY = blockIdx.y;
    const int tid = threadIdx.x;
    const float4* p4 = (const float4*)((isY ? Y : X) + (size_t)row * DDIM);
    __half* ph = (isY ? g_yh : g_xh) + (size_t)row * DDIM;

    float4 v = p4[tid];
    __half2 h0 = __floats2half2_rn(v.x, v.y);
    __half2 h1 = __floats2half2_rn(v.z, v.w);
    uint2 u = make_uint2(*(const uint32_t*)&h0, *(const uint32_t*)&h1);
    *(uint2*)(ph + tid * 4) = u;

    float a, b = 0.0f;
    if (isY) {
        a = v.x * v.x + v.y * v.y + v.z * v.z + v.w * v.w;
        b = v.x + v.y + v.z + v.w;
    } else {
        float ex = v.x + EPSV, ey = v.y + EPSV, ez = v.z + EPSV, ew = v.w + EPSV;
        a = ex * ex + ey * ey + ez * ez + ew * ew;
    }
    s1[tid] = a; s2[tid] = b;
    __syncthreads();
    for (int off = 128; off; off >>= 1) {
        if (tid < off) { s1[tid] += s1[tid + off]; s2[tid] += s2[tid + off]; }
        __syncthreads();
    }
    if (tid == 0) {
        if (isY) { g_ny[row] = s1[0]; g_sy[row] = s2[0]; }
        else     { g_nx[row] = s1[0]; }
    }
}

// ---------------------------------------------------------------------------
// fp16 mma.sync GEMM + distance epilogue (fp16 dist & distT, fp32 diagonal).
// 128x128 tile/CTA, 8 warps (4x2), warp tile 32x64, m16n8k16.
// 3-stage cp.async pipeline, one barrier per chunk.
// ---------------------------------------------------------------------------
__device__ __forceinline__ void issue_stage(__half* sA, __half* sB,
                                            const __half* gA, const __half* gB, int tid) {
#pragma unroll
    for (int i = 0; i < 4; i++) {
        const int idx = tid + i * 256;      // 0..1023
        const int r = idx >> 3;             // row 0..127
        const int c = (idx & 7) * 8;        // half col 0,8,..,56
        cp16(sA + r * PITCHH + c, gA + (size_t)r * DDIM + c);
        cp16(sB + r * PITCHH + c, gB + (size_t)r * DDIM + c);
    }
}

__global__ void __launch_bounds__(256, 2) gemm_mma_kernel() {
    extern __shared__ __half smh[];
    const int tid = threadIdx.x;
    const int wid = tid >> 5;
    const int lane = tid & 31;
    const int wm = wid & 3;          // warp row 0..3  (32 rows each)
    const int wn = wid >> 2;         // warp col 0..1  (64 cols each)
    const int g = lane >> 2;
    const int t = lane & 3;
    const int bi = blockIdx.y * BM;
    const int bj = blockIdx.x * BN;

    const __half* gA = g_xh + (size_t)bi * DDIM;
    const __half* gB = g_yh + (size_t)bj * DDIM;

    float acc[2][8][4];
#pragma unroll
    for (int mi = 0; mi < 2; mi++)
#pragma unroll
        for (int ni = 0; ni < 8; ni++)
#pragma unroll
            for (int e = 0; e < 4; e++) acc[mi][ni][e] = 0.0f;

    const int STAGE_H = 2 * 128 * PITCHH;    // halves per stage

    issue_stage(smh, smh + 128 * PITCHH, gA, gB, tid);
    CP_COMMIT();
    issue_stage(smh + STAGE_H, smh + STAGE_H + 128 * PITCHH,
                gA + BK, gB + BK, tid);
    CP_COMMIT();

    const int NCHUNK = DDIM / BK;    // 16
    for (int c = 0; c < NCHUNK; c++) {
        CP_WAIT1();
        __syncthreads();

        if (c + 2 < NCHUNK) {
            __half* nb = smh + ((c + 2) % NSTAGE) * STAGE_H;
            issue_stage(nb, nb + 128 * PITCHH,
                        gA + (c + 2) * BK, gB + (c + 2) * BK, tid);
        }
        CP_COMMIT();

        const uint32_t* sA = (const uint32_t*)(smh + (c % NSTAGE) * STAGE_H);
        const uint32_t* sB = sA + 128 * PITCHW;

#pragma unroll
        for (int ks = 0; ks < 4; ks++) {           // k = ks*16 .. ks*16+15
            const int k0 = ks * 8;                 // word offset
            uint32_t a[2][4], b[8][2];
#pragma unroll
            for (int mi = 0; mi < 2; mi++) {
                const int r0 = wm * 32 + mi * 16;
                a[mi][0] = sA[(r0 + g) * PITCHW + k0 + t];
                a[mi][1] = sA[(r0 + g + 8) * PITCHW + k0 + t];
                a[mi][2] = sA[(r0 + g) * PITCHW + k0 + t + 4];
                a[mi][3] = sA[(r0 + g + 8) * PITCHW + k0 + t + 4];
            }
#pragma unroll
            for (int ni = 0; ni < 8; ni++) {
                const int c0 = wn * 64 + ni * 8;
                b[ni][0] = sB[(c0 + g) * PITCHW + k0 + t];
                b[ni][1] = sB[(c0 + g) * PITCHW + k0 + t + 4];
            }
#pragma unroll
            for (int mi = 0; mi < 2; mi++)
#pragma unroll
                for (int ni = 0; ni < 8; ni++)
                    mma_f16(acc[mi][ni], a[mi], b[ni]);
        }
    }

    // -------- epilogue: regs -> smem tile (pitch 129 fp32) -> fp16 outputs ---
    __syncthreads();
    float* tile = (float*)smh;               // 128 x 129
    float* nx_s = tile + 128 * 129;
    float* ny_s = nx_s + 128;
    float* sy_s = ny_s + 128;
    if (tid < 128) {
        nx_s[tid] = g_nx[bi + tid];
        ny_s[tid] = g_ny[bj + tid];
        sy_s[tid] = g_sy[bj + tid];
    }
    __syncthreads();

#pragma unroll
    for (int mi = 0; mi < 2; mi++) {
        const int r0 = wm * 32 + mi * 16 + g;
#pragma unroll
        for (int ni = 0; ni < 8; ni++) {
            const int c0 = wn * 64 + ni * 8 + 2 * t;
#pragma unroll
            for (int e = 0; e < 4; e++) {
                const int row = r0 + (e >> 1) * 8;
                const int col = c0 + (e & 1);
                float sq = nx_s[row] + ny_s[col] - 2.0f * acc[mi][ni][e]
                           - 2.0f * EPSV * sy_s[col];
                tile[row * 129 + col] = sqrtf(fmaxf(sq, 0.0f));
            }
        }
    }
    __syncthreads();

    // fp32 diagonal (pos) for diagonal tiles
    if (blockIdx.x == blockIdx.y && tid < 128)
        g_diag[bi + tid] = tile[tid * 129 + tid];

    // dist: 4 halves per store (uint2), coalesced
    for (int i = tid; i < 128 * 32; i += 256) {
        const int rr = i >> 5;
        const int c4 = (i & 31) << 2;
        const float* tp = &tile[rr * 129 + c4];
        __half2 h0 = __floats2half2_rn(tp[0], tp[1]);
        __half2 h1 = __floats2half2_rn(tp[2], tp[3]);
        uint2 u = make_uint2(*(const uint32_t*)&h0, *(const uint32_t*)&h1);
        *(uint2*)&g_disth[(size_t)(bi + rr) * BDIM + bj + c4] = u;
    }
    // distT: conflict-free column reads, 2-byte coalesced stores
    for (int i = tid; i < 128 * 128; i += 256) {
        const int rr = i & 127;
        const int cc = i >> 7;
        g_distTh[(size_t)(bj + cc) * BDIM + bi + rr] = __float2half(tile[rr * 129 + cc]);
    }
}

// ---------------------------------------------------------------------------
// Per-row loss on fp16 distances (register-resident 16-bit radix select).
// [unchanged from round 9]
// ---------------------------------------------------------------------------
__global__ void __launch_bounds__(256) select_kernel() {
    __shared__ unsigned hist[256];
    __shared__ float wf[8];
    __shared__ unsigned wu[8];
    __shared__ unsigned wmp[8];
    __shared__ float s_t;
    __shared__ unsigned s_ctot;
    __shared__ float s_sall;
    __shared__ unsigned s_minp;
    __shared__ unsigned s_cd;
    __shared__ unsigned s_theta;

    const int row = blockIdx.x;
    const int tid = threadIdx.x;
    const int wid = tid >> 5;
    const int lane = tid & 31;
    const __half* mat = blockIdx.y ? g_distTh : g_disth;
    float* rl = g_rl + blockIdx.y * BDIM;
    const uint4* rp4 = (const uint4*)(mat + (size_t)row * BDIM);

    unsigned short hs[16];
    float fv[16];
#pragma unroll
    for (int q = 0; q < 2; q++) {
        uint4 u = rp4[tid + q * 256];
        const unsigned w[4] = {u.x, u.y, u.z, u.w};
#pragma unroll
        for (int j = 0; j < 4; j++) {
            hs[q * 8 + 2 * j]     = (unsigned short)(w[j] & 0xFFFFu);
            hs[q * 8 + 2 * j + 1] = (unsigned short)(w[j] >> 16);
        }
#pragma unroll
        for (int j = 0; j < 8; j++)
            fv[q * 8 + j] = __half2float(__ushort_as_half(hs[q * 8 + j]));
    }

    if (tid == 0) s_t = MARGINV + g_diag[row];

    {
        const int u4i = row >> 3;
        if ((u4i & 255) == tid) {
            const int slot = ((u4i >> 8) << 3) | (row & 7);
            hs[slot] = 0x7C00;
            fv[slot] = BIGV;
        }
    }
    __syncthreads();
    const float t = s_t;

    unsigned c = 0; float s = 0.0f; unsigned mnp = 0x7C00u;
#pragma unroll
    for (int j = 0; j < 16; j++) {
        const float v = fv[j];
        if (v < t) { c++; s += t - v; }
        mnp = min(mnp, (unsigned)hs[j]);
    }
#pragma unroll
    for (int off = 16; off; off >>= 1) {
        c += __shfl_down_sync(0xFFFFFFFFu, c, off);
        s += __shfl_down_sync(0xFFFFFFFFu, s, off);
        mnp = min(mnp, __shfl_down_sync(0xFFFFFFFFu, mnp, off));
    }
    if (lane == 0) { wu[wid] = c; wf[wid] = s; wmp[wid] = mnp; }
    __syncthreads();
    if (tid == 0) {
        unsigned ct = 0; float st = 0.0f; unsigned mt = 0x7C00u;
#pragma unroll
        for (int w = 0; w < 8; w++) { ct += wu[w]; st += wf[w]; mt = min(mt, wmp[w]); }
        s_ctot = ct; s_sall = st; s_minp = mt;
    }
    __syncthreads();

    if (s_ctot <= KSEL) {
        if (tid == 0) rl[row] = s_sall;
        return;
    }

    unsigned remk = KSEL;
    unsigned D = s_minp >> 8;
    for (;;) {
        unsigned cd = 0;
#pragma unroll
        for (int j = 0; j < 16; j++)
            cd += (((unsigned)hs[j] >> 8) == D);
#pragma unroll
        for (int off = 16; off; off >>= 1)
            cd += __shfl_down_sync(0xFFFFFFFFu, cd, off);
        if (lane == 0) wu[wid] = cd;
        __syncthreads();
        if (tid == 0) {
            unsigned ct = 0;
#pragma unroll
            for (int w = 0; w < 8; w++) ct += wu[w];
            s_cd = ct;
        }
        __syncthreads();
        const unsigned cdtot = s_cd;
        __syncthreads();
        if (cdtot >= remk) break;
        remk -= cdtot;
        D++;
    }

    hist[tid] = 0;
    __syncthreads();
#pragma unroll
    for (int j = 0; j < 16; j++) {
        const unsigned b = hs[j];
        if ((b >> 8) == D) atomicAdd(&hist[b & 255u], 1u);
    }
    __syncthreads();
    if (tid < 32) {
        unsigned loc[8]; unsigned lsum = 0;
#pragma unroll
        for (int j = 0; j < 8; j++) { loc[j] = hist[tid * 8 + j]; lsum += loc[j]; }
        unsigned incl = lsum;
#pragma unroll
        for (int off = 1; off < 32; off <<= 1) {
            unsigned y = __shfl_up_sync(0xFFFFFFFFu, incl, off);
            if (tid >= off) incl += y;
        }
        const unsigned excl = incl - lsum;
        if (excl < remk && incl >= remk) {
            unsigned cum = excl;
#pragma unroll
            for (int j = 0; j < 8; j++) {
                if (cum + loc[j] >= remk) {
                    s_theta = (D << 8) | (unsigned)(tid * 8 + j);
                    break;
                }
                cum += loc[j];
            }
        }
    }
    __syncthreads();
    const unsigned theta_pat = s_theta;
    const float theta = __half2float(__ushort_as_half((unsigned short)theta_pat));

    unsigned cl = 0; float sl = 0.0f;
#pragma unroll
    for (int j = 0; j < 16; j++) {
        if ((unsigned)hs[j] < theta_pat) { cl++; sl += fv[j]; }
    }
#pragma unroll
    for (int off = 16; off; off >>= 1) {
        cl += __shfl_down_sync(0xFFFFFFFFu, cl, off);
        sl += __shfl_down_sync(0xFFFFFFFFu, sl, off);
    }
    if (lane == 0) { wu[wid] = cl; wf[wid] = sl; }
    __syncthreads();
    if (tid == 0) {
        unsigned ct = 0; float st = 0.0f;
#pragma unroll
        for (int w = 0; w < 8; w++) { ct += wu[w]; st += wf[w]; }
        rl[row] = (float)KSEL * t - st - (float)(KSEL - ct) * theta;
    }
}

// ---------------------------------------------------------------------------
__global__ void finalize_kernel(float* __restrict__ out) {
    __shared__ float sm[256];
    for (int which = 0; which < 2; which++) {
        float s = 0.0f;
        for (int i = threadIdx.x; i < BDIM; i += 256) s += g_rl[which * BDIM + i];
        sm[threadIdx.x] = s;
        __syncthreads();
        for (int off = 128; off; off >>= 1) {
            if (threadIdx.x < off) sm[threadIdx.x] += sm[threadIdx.x + off];
            __syncthreads();
        }
        if (threadIdx.x == 0) out[which] = sm[0] / ((float)BDIM * (float)KSEL);
        __syncthreads();
    }
}

// ---------------------------------------------------------------------------
extern "C" void kernel_launch(void* const* d_in, const int* in_sizes, int n_in,
                              void* d_out, int out_size) {
    const float* X = (const float*)d_in[0];
    const float* Y = (const float*)d_in[1];
    float* out = (float*)d_out;

    cudaFuncSetAttribute(gemm_mma_kernel, cudaFuncAttributeMaxDynamicSharedMemorySize,
                         GEMM_SMEM);

    norms_kernel<<<dim3(BDIM, 2), 256>>>(X, Y);
    gemm_mma_kernel<<<dim3(BDIM / BN, BDIM / BM), 256, GEMM_SMEM>>>();
    select_kernel<<<dim3(BDIM, 2), 256>>>();
    finalize_kernel<<<1, 256>>>(out);
}

// round 12
// speedup vs baseline: 1.5514x; 1.0322x over previous
#include <cuda_runtime.h>
#include <cuda_fp16.h>
#include <math.h>
#include <stdint.h>

#define BDIM 4096
#define DDIM 1024
#define KSEL 1024
#define EPSV 1e-6f
#define MARGINV 0.5f
#define BIGV 1.0e6f

// ---------------- scratch (device globals; allocation-free) ----------------
__device__ __half g_disth[(size_t)BDIM * BDIM];   // 32 MB
__device__ __half g_distTh[(size_t)BDIM * BDIM];  // 32 MB
__device__ float g_diag[BDIM];                    // fp32 diagonal (pos)
__device__ __half g_xh[(size_t)BDIM * DDIM];      // fp16-rounded X (8 MB)
__device__ __half g_yh[(size_t)BDIM * DDIM];      // fp16-rounded Y (8 MB)
__device__ float g_nx[BDIM];
__device__ float g_ny[BDIM];
__device__ float g_sy[BDIM];
__device__ float g_rl[2 * BDIM];

// ---------------- helpers ----------------
__device__ __forceinline__ uint32_t smem_u32(const void* p) {
    uint32_t a;
    asm("{ .reg .u64 t; cvta.to.shared.u64 t, %1; cvt.u32.u64 %0, t; }" : "=r"(a) : "l"(p));
    return a;
}
__device__ __forceinline__ void cp16(void* dst, const void* src) {
    uint32_t d = smem_u32(dst);
    asm volatile("cp.async.cg.shared.global [%0], [%1], 16;" :: "r"(d), "l"(src));
}
#define CP_COMMIT() asm volatile("cp.async.commit_group;")
#define CP_WAIT1()  asm volatile("cp.async.wait_group 1;")

// fp16 mma: D(16x8,f32) += A(16x16,f16) * B(16x8,f16)
__device__ __forceinline__ void mma_f16(float* c, const uint32_t* a, const uint32_t* b) {
    asm volatile(
        "mma.sync.aligned.m16n8k16.row.col.f32.f16.f16.f32 "
        "{%0,%1,%2,%3}, {%4,%5,%6,%7}, {%8,%9}, {%0,%1,%2,%3};"
        : "+f"(c[0]), "+f"(c[1]), "+f"(c[2]), "+f"(c[3])
        : "r"(a[0]), "r"(a[1]), "r"(a[2]), "r"(a[3]), "r"(b[0]), "r"(b[1]));
}

__device__ __forceinline__ void ldsm_x4(uint32_t& r0, uint32_t& r1, uint32_t& r2,
                                        uint32_t& r3, uint32_t addr) {
    asm volatile("ldmatrix.sync.aligned.m8n8.x4.shared.b16 {%0,%1,%2,%3}, [%4];"
                 : "=r"(r0), "=r"(r1), "=r"(r2), "=r"(r3) : "r"(addr));
}

// ---------------- GEMM config ----------------
#define BM 128
#define BN 128
#define BK 64                              // halves per k-chunk (128 B rows)
#define PITCHH 72                          // halves per smem row (144 B)
#define PITCHW 36                          // words per smem row
#define STAGE_BYTES (2 * 128 * PITCHH * 2) // A+B per stage = 36864 B
#define NSTAGE 3
#define GEMM_SMEM (NSTAGE * STAGE_BYTES)   // 110592 B

// ---------------------------------------------------------------------------
// Norms + fp16 pre-rounding (one float4 per thread)
// ---------------------------------------------------------------------------
__global__ void __launch_bounds__(256) norms_kernel(const float* __restrict__ X,
                                                    const float* __restrict__ Y) {
    __shared__ float s1[256], s2[256];
    const int row = blockIdx.x;
    const int isY = blockIdx.y;
    const int tid = threadIdx.x;
    const float4* p4 = (const float4*)((isY ? Y : X) + (size_t)row * DDIM);
    __half* ph = (isY ? g_yh : g_xh) + (size_t)row * DDIM;

    float4 v = p4[tid];
    __half2 h0 = __floats2half2_rn(v.x, v.y);
    __half2 h1 = __floats2half2_rn(v.z, v.w);
    uint2 u = make_uint2(*(const uint32_t*)&h0, *(const uint32_t*)&h1);
    *(uint2*)(ph + tid * 4) = u;

    float a, b = 0.0f;
    if (isY) {
        a = v.x * v.x + v.y * v.y + v.z * v.z + v.w * v.w;
        b = v.x + v.y + v.z + v.w;
    } else {
        float ex = v.x + EPSV, ey = v.y + EPSV, ez = v.z + EPSV, ew = v.w + EPSV;
        a = ex * ex + ey * ey + ez * ez + ew * ew;
    }
    s1[tid] = a; s2[tid] = b;
    __syncthreads();
    for (int off = 128; off; off >>= 1) {
        if (tid < off) { s1[tid] += s1[tid + off]; s2[tid] += s2[tid + off]; }
        __syncthreads();
    }
    if (tid == 0) {
        if (isY) { g_ny[row] = s1[0]; g_sy[row] = s2[0]; }
        else     { g_nx[row] = s1[0]; }
    }
}

// ---------------------------------------------------------------------------
// fp16 mma.sync GEMM with ldmatrix fragment loads + distance epilogue.
// 128x128 tile/CTA, 8 warps (4x2), warp tile 32x64, m16n8k16.
// 3-stage cp.async pipeline, one barrier per chunk.
// Per ks: 2 ldmatrix.x4 (A) + 4 ldmatrix.x4 (B) + 16 MMA.
// ---------------------------------------------------------------------------
__device__ __forceinline__ void issue_stage(__half* sA, __half* sB,
                                            const __half* gA, const __half* gB, int tid) {
#pragma unroll
    for (int i = 0; i < 4; i++) {
        const int idx = tid + i * 256;      // 0..1023
        const int r = idx >> 3;             // row 0..127
        const int c = (idx & 7) * 8;        // half col 0,8,..,56
        cp16(sA + r * PITCHH + c, gA + (size_t)r * DDIM + c);
        cp16(sB + r * PITCHH + c, gB + (size_t)r * DDIM + c);
    }
}

__global__ void __launch_bounds__(256, 2) gemm_mma_kernel() {
    extern __shared__ __half smh[];
    const uint32_t sbase = smem_u32(smh);
    const int tid = threadIdx.x;
    const int wid = tid >> 5;
    const int lane = tid & 31;
    const int wm = wid & 3;          // warp row 0..3  (32 rows each)
    const int wn = wid >> 2;         // warp col 0..1  (64 cols each)
    const int g = lane >> 2;
    const int t = lane & 3;
    const int bi = blockIdx.y * BM;
    const int bj = blockIdx.x * BN;

    const __half* gA = g_xh + (size_t)bi * DDIM;
    const __half* gB = g_yh + (size_t)bj * DDIM;

    float acc[2][8][4];
#pragma unroll
    for (int mi = 0; mi < 2; mi++)
#pragma unroll
        for (int ni = 0; ni < 8; ni++)
#pragma unroll
            for (int e = 0; e < 4; e++) acc[mi][ni][e] = 0.0f;

    const int STAGE_H = 2 * 128 * PITCHH;    // halves per stage
    const uint32_t B_OFF = 128 * PITCHH * 2; // bytes from stage start to B

    // per-lane ldmatrix address offsets (bytes from stage/B base)
    const int mrow = lane & 7;
    const int mm = lane >> 3;                 // matrix index 0..3
    // A: matrices {rows+0,k0},{rows+8,k0},{rows+0,k0+4w},{rows+8,k0+4w}
    const uint32_t aOff = (uint32_t)(((wm * 32 + mrow + (mm & 1) * 8) * PITCHW
                                      + (mm >> 1) * 4) * 4);
    // B: matrices {rows+0,k0},{rows+0,k0+4w},{rows+8,k0},{rows+8,k0+4w}
    const uint32_t bOff = (uint32_t)(((wn * 64 + mrow + (mm >> 1) * 8) * PITCHW
                                      + (mm & 1) * 4) * 4);

    issue_stage(smh, smh + 128 * PITCHH, gA, gB, tid);
    CP_COMMIT();
    issue_stage(smh + STAGE_H, smh + STAGE_H + 128 * PITCHH,
                gA + BK, gB + BK, tid);
    CP_COMMIT();

    const int NCHUNK = DDIM / BK;    // 16
    for (int c = 0; c < NCHUNK; c++) {
        CP_WAIT1();
        __syncthreads();

        if (c + 2 < NCHUNK) {
            __half* nb = smh + ((c + 2) % NSTAGE) * STAGE_H;
            issue_stage(nb, nb + 128 * PITCHH,
                        gA + (c + 2) * BK, gB + (c + 2) * BK, tid);
        }
        CP_COMMIT();

        const uint32_t stg = sbase + (uint32_t)((c % NSTAGE) * STAGE_BYTES);
        const uint32_t aBase = stg + aOff;
        const uint32_t bBase = stg + B_OFF + bOff;

#pragma unroll
        for (int ks = 0; ks < 4; ks++) {           // k = ks*16 .. ks*16+15
            const uint32_t kb = (uint32_t)(ks * 32);   // 8 words = 32 bytes
            uint32_t a[2][4], b[8][2];
            ldsm_x4(a[0][0], a[0][1], a[0][2], a[0][3], aBase + kb);
            ldsm_x4(a[1][0], a[1][1], a[1][2], a[1][3],
                    aBase + kb + 16 * PITCHW * 4);
#pragma unroll
            for (int p = 0; p < 4; p++) {
                ldsm_x4(b[2 * p][0], b[2 * p][1], b[2 * p + 1][0], b[2 * p + 1][1],
                        bBase + kb + (uint32_t)(p * 16 * PITCHW * 4));
            }
#pragma unroll
            for (int mi = 0; mi < 2; mi++)
#pragma unroll
                for (int ni = 0; ni < 8; ni++)
                    mma_f16(acc[mi][ni], a[mi], b[ni]);
        }
    }

    // -------- epilogue: regs -> smem tile (pitch 129 fp32) -> fp16 outputs ---
    __syncthreads();
    float* tile = (float*)smh;               // 128 x 129
    float* nx_s = tile + 128 * 129;
    float* ny_s = nx_s + 128;
    float* sy_s = ny_s + 128;
    if (tid < 128) {
        nx_s[tid] = g_nx[bi + tid];
        ny_s[tid] = g_ny[bj + tid];
        sy_s[tid] = g_sy[bj + tid];
    }
    __syncthreads();

#pragma unroll
    for (int mi = 0; mi < 2; mi++) {
        const int r0 = wm * 32 + mi * 16 + g;
#pragma unroll
        for (int ni = 0; ni < 8; ni++) {
            const int c0 = wn * 64 + ni * 8 + 2 * t;
#pragma unroll
            for (int e = 0; e < 4; e++) {
                const int row = r0 + (e >> 1) * 8;
                const int col = c0 + (e & 1);
                float sq = nx_s[row] + ny_s[col] - 2.0f * acc[mi][ni][e]
                           - 2.0f * EPSV * sy_s[col];
                tile[row * 129 + col] = sqrtf(fmaxf(sq, 0.0f));
            }
        }
    }
    __syncthreads();

    // fp32 diagonal (pos) for diagonal tiles
    if (blockIdx.x == blockIdx.y && tid < 128)
        g_diag[bi + tid] = tile[tid * 129 + tid];

    // dist: 4 halves per store (uint2), coalesced
    for (int i = tid; i < 128 * 32; i += 256) {
        const int rr = i >> 5;
        const int c4 = (i & 31) << 2;
        const float* tp = &tile[rr * 129 + c4];
        __half2 h0 = __floats2half2_rn(tp[0], tp[1]);
        __half2 h1 = __floats2half2_rn(tp[2], tp[3]);
        uint2 u = make_uint2(*(const uint32_t*)&h0, *(const uint32_t*)&h1);
        *(uint2*)&g_disth[(size_t)(bi + rr) * BDIM + bj + c4] = u;
    }
    // distT: conflict-free column reads, 2-byte coalesced stores
    for (int i = tid; i < 128 * 128; i += 256) {
        const int rr = i & 127;
        const int cc = i >> 7;
        g_distTh[(size_t)(bj + cc) * BDIM + bi + rr] = __float2half(tile[rr * 129 + cc]);
    }
}

// ---------------------------------------------------------------------------
// Per-row loss on fp16 distances (register-resident 16-bit radix select).
// [unchanged from round 9]
// ---------------------------------------------------------------------------
__global__ void __launch_bounds__(256) select_kernel() {
    __shared__ unsigned hist[256];
    __shared__ float wf[8];
    __shared__ unsigned wu[8];
    __shared__ unsigned wmp[8];
    __shared__ float s_t;
    __shared__ unsigned s_ctot;
    __shared__ float s_sall;
    __shared__ unsigned s_minp;
    __shared__ unsigned s_cd;
    __shared__ unsigned s_theta;

    const int row = blockIdx.x;
    const int tid = threadIdx.x;
    const int wid = tid >> 5;
    const int lane = tid & 31;
    const __half* mat = blockIdx.y ? g_distTh : g_disth;
    float* rl = g_rl + blockIdx.y * BDIM;
    const uint4* rp4 = (const uint4*)(mat + (size_t)row * BDIM);

    unsigned short hs[16];
    float fv[16];
#pragma unroll
    for (int q = 0; q < 2; q++) {
        uint4 u = rp4[tid + q * 256];
        const unsigned w[4] = {u.x, u.y, u.z, u.w};
#pragma unroll
        for (int j = 0; j < 4; j++) {
            hs[q * 8 + 2 * j]     = (unsigned short)(w[j] & 0xFFFFu);
            hs[q * 8 + 2 * j + 1] = (unsigned short)(w[j] >> 16);
        }
#pragma unroll
        for (int j = 0; j < 8; j++)
            fv[q * 8 + j] = __half2float(__ushort_as_half(hs[q * 8 + j]));
    }

    if (tid == 0) s_t = MARGINV + g_diag[row];

    {
        const int u4i = row >> 3;
        if ((u4i & 255) == tid) {
            const int slot = ((u4i >> 8) << 3) | (row & 7);
            hs[slot] = 0x7C00;
            fv[slot] = BIGV;
        }
    }
    __syncthreads();
    const float t = s_t;

    unsigned c = 0; float s = 0.0f; unsigned mnp = 0x7C00u;
#pragma unroll
    for (int j = 0; j < 16; j++) {
        const float v = fv[j];
        if (v < t) { c++; s += t - v; }
        mnp = min(mnp, (unsigned)hs[j]);
    }
#pragma unroll
    for (int off = 16; off; off >>= 1) {
        c += __shfl_down_sync(0xFFFFFFFFu, c, off);
        s += __shfl_down_sync(0xFFFFFFFFu, s, off);
        mnp = min(mnp, __shfl_down_sync(0xFFFFFFFFu, mnp, off));
    }
    if (lane == 0) { wu[wid] = c; wf[wid] = s; wmp[wid] = mnp; }
    __syncthreads();
    if (tid == 0) {
        unsigned ct = 0; float st = 0.0f; unsigned mt = 0x7C00u;
#pragma unroll
        for (int w = 0; w < 8; w++) { ct += wu[w]; st += wf[w]; mt = min(mt, wmp[w]); }
        s_ctot = ct; s_sall = st; s_minp = mt;
    }
    __syncthreads();

    if (s_ctot <= KSEL) {
        if (tid == 0) rl[row] = s_sall;
        return;
    }

    unsigned remk = KSEL;
    unsigned D = s_minp >> 8;
    for (;;) {
        unsigned cd = 0;
#pragma unroll
        for (int j = 0; j < 16; j++)
            cd += (((unsigned)hs[j] >> 8) == D);
#pragma unroll
        for (int off = 16; off; off >>= 1)
            cd += __shfl_down_sync(0xFFFFFFFFu, cd, off);
        if (lane == 0) wu[wid] = cd;
        __syncthreads();
        if (tid == 0) {
            unsigned ct = 0;
#pragma unroll
            for (int w = 0; w < 8; w++) ct += wu[w];
            s_cd = ct;
        }
        __syncthreads();
        const unsigned cdtot = s_cd;
        __syncthreads();
        if (cdtot >= remk) break;
        remk -= cdtot;
        D++;
    }

    hist[tid] = 0;
    __syncthreads();
#pragma unroll
    for (int j = 0; j < 16; j++) {
        const unsigned b = hs[j];
        if ((b >> 8) == D) atomicAdd(&hist[b & 255u], 1u);
    }
    __syncthreads();
    if (tid < 32) {
        unsigned loc[8]; unsigned lsum = 0;
#pragma unroll
        for (int j = 0; j < 8; j++) { loc[j] = hist[tid * 8 + j]; lsum += loc[j]; }
        unsigned incl = lsum;
#pragma unroll
        for (int off = 1; off < 32; off <<= 1) {
            unsigned y = __shfl_up_sync(0xFFFFFFFFu, incl, off);
            if (tid >= off) incl += y;
        }
        const unsigned excl = incl - lsum;
        if (excl < remk && incl >= remk) {
            unsigned cum = excl;
#pragma unroll
            for (int j = 0; j < 8; j++) {
                if (cum + loc[j] >= remk) {
                    s_theta = (D << 8) | (unsigned)(tid * 8 + j);
                    break;
                }
                cum += loc[j];
            }
        }
    }
    __syncthreads();
    const unsigned theta_pat = s_theta;
    const float theta = __half2float(__ushort_as_half((unsigned short)theta_pat));

    unsigned cl = 0; float sl = 0.0f;
#pragma unroll
    for (int j = 0; j < 16; j++) {
        if ((unsigned)hs[j] < theta_pat) { cl++; sl += fv[j]; }
    }
#pragma unroll
    for (int off = 16; off; off >>= 1) {
        cl += __shfl_down_sync(0xFFFFFFFFu, cl, off);
        sl += __shfl_down_sync(0xFFFFFFFFu, sl, off);
    }
    if (lane == 0) { wu[wid] = cl; wf[wid] = sl; }
    __syncthreads();
    if (tid == 0) {
        unsigned ct = 0; float st = 0.0f;
#pragma unroll
        for (int w = 0; w < 8; w++) { ct += wu[w]; st += wf[w]; }
        rl[row] = (float)KSEL * t - st - (float)(KSEL - ct) * theta;
    }
}

// ---------------------------------------------------------------------------
__global__ void finalize_kernel(float* __restrict__ out) {
    __shared__ float sm[256];
    for (int which = 0; which < 2; which++) {
        float s = 0.0f;
        for (int i = threadIdx.x; i < BDIM; i += 256) s += g_rl[which * BDIM + i];
        sm[threadIdx.x] = s;
        __syncthreads();
        for (int off = 128; off; off >>= 1) {
            if (threadIdx.x < off) sm[threadIdx.x] += sm[threadIdx.x + off];
            __syncthreads();
        }
        if (threadIdx.x == 0) out[which] = sm[0] / ((float)BDIM * (float)KSEL);
        __syncthreads();
    }
}

// ---------------------------------------------------------------------------
extern "C" void kernel_launch(void* const* d_in, const int* in_sizes, int n_in,
                              void* d_out, int out_size) {
    const float* X = (const float*)d_in[0];
    const float* Y = (const float*)d_in[1];
    float* out = (float*)d_out;

    cudaFuncSetAttribute(gemm_mma_kernel, cudaFuncAttributeMaxDynamicSharedMemorySize,
                         GEMM_SMEM);

    norms_kernel<<<dim3(BDIM, 2), 256>>>(X, Y);
    gemm_mma_kernel<<<dim3(BDIM / BN, BDIM / BM), 256, GEMM_SMEM>>>();
    select_kernel<<<dim3(BDIM, 2), 256>>>();
    finalize_kernel<<<1, 256>>>(out);
}

// round 13
// speedup vs baseline: 1.7585x; 1.1335x over previous
#include <cuda_runtime.h>
#include <cuda_fp16.h>
#include <math.h>
#include <stdint.h>

#define BDIM 4096
#define DDIM 1024
#define KSEL 1024
#define EPSV 1e-6f
#define MARGINV 0.5f
#define BIGV 1.0e6f

// ---------------- scratch (device globals; allocation-free) ----------------
__device__ __half g_disth[(size_t)BDIM * BDIM];   // 32 MB
__device__ __half g_distTh[(size_t)BDIM * BDIM];  // 32 MB
__device__ float g_diag[BDIM];                    // fp32 diagonal (pos)
__device__ __half g_xh[(size_t)BDIM * DDIM];      // fp16-rounded X (8 MB)
__device__ __half g_yh[(size_t)BDIM * DDIM];      // fp16-rounded Y (8 MB)
__device__ float g_nx[BDIM];
__device__ float g_ny[BDIM];
__device__ float g_sy[BDIM];
__device__ float g_rl[2 * BDIM];

// ---------------- helpers ----------------
__device__ __forceinline__ uint32_t smem_u32(const void* p) {
    uint32_t a;
    asm("{ .reg .u64 t; cvta.to.shared.u64 t, %1; cvt.u32.u64 %0, t; }" : "=r"(a) : "l"(p));
    return a;
}
__device__ __forceinline__ void cp16(void* dst, const void* src) {
    uint32_t d = smem_u32(dst);
    asm volatile("cp.async.cg.shared.global [%0], [%1], 16;" :: "r"(d), "l"(src));
}
#define CP_COMMIT() asm volatile("cp.async.commit_group;")
#define CP_WAIT1()  asm volatile("cp.async.wait_group 1;")

// fp16 mma: D(16x8,f32) += A(16x16,f16) * B(16x8,f16)
__device__ __forceinline__ void mma_f16(float* c, const uint32_t* a, const uint32_t* b) {
    asm volatile(
        "mma.sync.aligned.m16n8k16.row.col.f32.f16.f16.f32 "
        "{%0,%1,%2,%3}, {%4,%5,%6,%7}, {%8,%9}, {%0,%1,%2,%3};"
        : "+f"(c[0]), "+f"(c[1]), "+f"(c[2]), "+f"(c[3])
        : "r"(a[0]), "r"(a[1]), "r"(a[2]), "r"(a[3]), "r"(b[0]), "r"(b[1]));
}

__device__ __forceinline__ void ldsm_x4(uint32_t& r0, uint32_t& r1, uint32_t& r2,
                                        uint32_t& r3, uint32_t addr) {
    asm volatile("ldmatrix.sync.aligned.m8n8.x4.shared.b16 {%0,%1,%2,%3}, [%4];"
                 : "=r"(r0), "=r"(r1), "=r"(r2), "=r"(r3) : "r"(addr));
}

__device__ __forceinline__ float pat2f(unsigned p) {
    return __half2float(__ushort_as_half((unsigned short)p));
}

// ---------------- GEMM config ----------------
#define BM 128
#define BN 128
#define BK 64                              // halves per k-chunk (128 B rows)
#define PITCHH 72                          // halves per smem row (144 B)
#define PITCHW 36                          // words per smem row
#define STAGE_BYTES (2 * 128 * PITCHH * 2) // A+B per stage = 36864 B
#define NSTAGE 3
#define GEMM_SMEM (NSTAGE * STAGE_BYTES)   // 110592 B

// ---------------------------------------------------------------------------
// Norms + fp16 pre-rounding (one float4 per thread)  [unchanged]
// ---------------------------------------------------------------------------
__global__ void __launch_bounds__(256) norms_kernel(const float* __restrict__ X,
                                                    const float* __restrict__ Y) {
    __shared__ float s1[256], s2[256];
    const int row = blockIdx.x;
    const int isY = blockIdx.y;
    const int tid = threadIdx.x;
    const float4* p4 = (const float4*)((isY ? Y : X) + (size_t)row * DDIM);
    __half* ph = (isY ? g_yh : g_xh) + (size_t)row * DDIM;

    float4 v = p4[tid];
    __half2 h0 = __floats2half2_rn(v.x, v.y);
    __half2 h1 = __floats2half2_rn(v.z, v.w);
    uint2 u = make_uint2(*(const uint32_t*)&h0, *(const uint32_t*)&h1);
    *(uint2*)(ph + tid * 4) = u;

    float a, b = 0.0f;
    if (isY) {
        a = v.x * v.x + v.y * v.y + v.z * v.z + v.w * v.w;
        b = v.x + v.y + v.z + v.w;
    } else {
        float ex = v.x + EPSV, ey = v.y + EPSV, ez = v.z + EPSV, ew = v.w + EPSV;
        a = ex * ex + ey * ey + ez * ez + ew * ew;
    }
    s1[tid] = a; s2[tid] = b;
    __syncthreads();
    for (int off = 128; off; off >>= 1) {
        if (tid < off) { s1[tid] += s1[tid + off]; s2[tid] += s2[tid + off]; }
        __syncthreads();
    }
    if (tid == 0) {
        if (isY) { g_ny[row] = s1[0]; g_sy[row] = s2[0]; }
        else     { g_nx[row] = s1[0]; }
    }
}

// ---------------------------------------------------------------------------
// fp16 mma.sync GEMM with ldmatrix fragment loads + distance epilogue.
// [byte-identical to round 12]
// ---------------------------------------------------------------------------
__device__ __forceinline__ void issue_stage(__half* sA, __half* sB,
                                            const __half* gA, const __half* gB, int tid) {
#pragma unroll
    for (int i = 0; i < 4; i++) {
        const int idx = tid + i * 256;      // 0..1023
        const int r = idx >> 3;             // row 0..127
        const int c = (idx & 7) * 8;        // half col 0,8,..,56
        cp16(sA + r * PITCHH + c, gA + (size_t)r * DDIM + c);
        cp16(sB + r * PITCHH + c, gB + (size_t)r * DDIM + c);
    }
}

__global__ void __launch_bounds__(256, 2) gemm_mma_kernel() {
    extern __shared__ __half smh[];
    const uint32_t sbase = smem_u32(smh);
    const int tid = threadIdx.x;
    const int wid = tid >> 5;
    const int lane = tid & 31;
    const int wm = wid & 3;
    const int wn = wid >> 2;
    const int g = lane >> 2;
    const int t = lane & 3;
    const int bi = blockIdx.y * BM;
    const int bj = blockIdx.x * BN;

    const __half* gA = g_xh + (size_t)bi * DDIM;
    const __half* gB = g_yh + (size_t)bj * DDIM;

    float acc[2][8][4];
#pragma unroll
    for (int mi = 0; mi < 2; mi++)
#pragma unroll
        for (int ni = 0; ni < 8; ni++)
#pragma unroll
            for (int e = 0; e < 4; e++) acc[mi][ni][e] = 0.0f;

    const int STAGE_H = 2 * 128 * PITCHH;
    const uint32_t B_OFF = 128 * PITCHH * 2;

    const int mrow = lane & 7;
    const int mm = lane >> 3;
    const uint32_t aOff = (uint32_t)(((wm * 32 + mrow + (mm & 1) * 8) * PITCHW
                                      + (mm >> 1) * 4) * 4);
    const uint32_t bOff = (uint32_t)(((wn * 64 + mrow + (mm >> 1) * 8) * PITCHW
                                      + (mm & 1) * 4) * 4);

    issue_stage(smh, smh + 128 * PITCHH, gA, gB, tid);
    CP_COMMIT();
    issue_stage(smh + STAGE_H, smh + STAGE_H + 128 * PITCHH,
                gA + BK, gB + BK, tid);
    CP_COMMIT();

    const int NCHUNK = DDIM / BK;    // 16
    for (int c = 0; c < NCHUNK; c++) {
        CP_WAIT1();
        __syncthreads();

        if (c + 2 < NCHUNK) {
            __half* nb = smh + ((c + 2) % NSTAGE) * STAGE_H;
            issue_stage(nb, nb + 128 * PITCHH,
                        gA + (c + 2) * BK, gB + (c + 2) * BK, tid);
        }
        CP_COMMIT();

        const uint32_t stg = sbase + (uint32_t)((c % NSTAGE) * STAGE_BYTES);
        const uint32_t aBase = stg + aOff;
        const uint32_t bBase = stg + B_OFF + bOff;

#pragma unroll
        for (int ks = 0; ks < 4; ks++) {
            const uint32_t kb = (uint32_t)(ks * 32);
            uint32_t a[2][4], b[8][2];
            ldsm_x4(a[0][0], a[0][1], a[0][2], a[0][3], aBase + kb);
            ldsm_x4(a[1][0], a[1][1], a[1][2], a[1][3],
                    aBase + kb + 16 * PITCHW * 4);
#pragma unroll
            for (int p = 0; p < 4; p++) {
                ldsm_x4(b[2 * p][0], b[2 * p][1], b[2 * p + 1][0], b[2 * p + 1][1],
                        bBase + kb + (uint32_t)(p * 16 * PITCHW * 4));
            }
#pragma unroll
            for (int mi = 0; mi < 2; mi++)
#pragma unroll
                for (int ni = 0; ni < 8; ni++)
                    mma_f16(acc[mi][ni], a[mi], b[ni]);
        }
    }

    __syncthreads();
    float* tile = (float*)smh;
    float* nx_s = tile + 128 * 129;
    float* ny_s = nx_s + 128;
    float* sy_s = ny_s + 128;
    if (tid < 128) {
        nx_s[tid] = g_nx[bi + tid];
        ny_s[tid] = g_ny[bj + tid];
        sy_s[tid] = g_sy[bj + tid];
    }
    __syncthreads();

#pragma unroll
    for (int mi = 0; mi < 2; mi++) {
        const int r0 = wm * 32 + mi * 16 + g;
#pragma unroll
        for (int ni = 0; ni < 8; ni++) {
            const int c0 = wn * 64 + ni * 8 + 2 * t;
#pragma unroll
            for (int e = 0; e < 4; e++) {
                const int row = r0 + (e >> 1) * 8;
                const int col = c0 + (e & 1);
                float sq = nx_s[row] + ny_s[col] - 2.0f * acc[mi][ni][e]
                           - 2.0f * EPSV * sy_s[col];
                tile[row * 129 + col] = sqrtf(fmaxf(sq, 0.0f));
            }
        }
    }
    __syncthreads();

    if (blockIdx.x == blockIdx.y && tid < 128)
        g_diag[bi + tid] = tile[tid * 129 + tid];

    for (int i = tid; i < 128 * 32; i += 256) {
        const int rr = i >> 5;
        const int c4 = (i & 31) << 2;
        const float* tp = &tile[rr * 129 + c4];
        __half2 h0 = __floats2half2_rn(tp[0], tp[1]);
        __half2 h1 = __floats2half2_rn(tp[2], tp[3]);
        uint2 u = make_uint2(*(const uint32_t*)&h0, *(const uint32_t*)&h1);
        *(uint2*)&g_disth[(size_t)(bi + rr) * BDIM + bj + c4] = u;
    }
    for (int i = tid; i < 128 * 128; i += 256) {
        const int rr = i & 127;
        const int cc = i >> 7;
        g_distTh[(size_t)(bj + cc) * BDIM + bi + rr] = __float2half(tile[rr * 129 + cc]);
    }
}

// ---------------------------------------------------------------------------
// Per-row loss on fp16 distances. Pattern-only register state (8 packed u32),
// integer compares for all selection sweeps (valid: all patterns are
// non-negative halves), on-demand conversion only for conditional sums.
// Hinge sum via c*t - sum(v). redux.sync for u32 reductions.
// grid (BDIM, 2): y=0 rows of dist (loss_xy), y=1 rows of distT (loss_yx).
// ---------------------------------------------------------------------------
__global__ void __launch_bounds__(256) select_kernel() {
    __shared__ unsigned hist[256];
    __shared__ float wf[8];
    __shared__ unsigned wu[8];
    __shared__ float s_t;
    __shared__ unsigned s_ctot;
    __shared__ float s_sall;
    __shared__ unsigned s_minp;
    __shared__ unsigned s_cd;
    __shared__ unsigned s_theta;

    const int row = blockIdx.x;
    const int tid = threadIdx.x;
    const int wid = tid >> 5;
    const int lane = tid & 31;
    const __half* mat = blockIdx.y ? g_distTh : g_disth;
    float* rl = g_rl + blockIdx.y * BDIM;
    const uint4* rp4 = (const uint4*)(mat + (size_t)row * BDIM);

    // 16 halves per thread as 8 packed u32
    unsigned rv[8];
    {
        uint4 u0 = rp4[tid];
        uint4 u1 = rp4[tid + 256];
        rv[0] = u0.x; rv[1] = u0.y; rv[2] = u0.z; rv[3] = u0.w;
        rv[4] = u1.x; rv[5] = u1.y; rv[6] = u1.z; rv[7] = u1.w;
    }

    if (tid == 0) s_t = MARGINV + g_diag[row];

    // patch diagonal to +inf pattern in the owning thread's register copy
    {
        const int u4i = row >> 3;                // uint4 index of diagonal
        if ((u4i & 255) == tid) {
            const int w = ((u4i >> 8) << 2) | ((row >> 1) & 3);  // packed reg
            if (row & 1) rv[w] = (rv[w] & 0x0000FFFFu) | 0x7C000000u;
            else         rv[w] = (rv[w] & 0xFFFF0000u) | 0x00007C00u;
        }
    }
    __syncthreads();
    const float t = s_t;

    // pattern threshold: v < t  <=>  pat(v) < tcmp
    unsigned tcmp;
    {
        const __half thd = __float2half_rd(t);
        tcmp = (unsigned)__half_as_ushort(thd) + (t > __half2float(thd) ? 1u : 0u);
    }

    // ---- fused sweep: count & sum of v below t, min pattern ----
    unsigned c = 0; float s = 0.0f; unsigned mnp = 0x7C00u;
#pragma unroll
    for (int w = 0; w < 8; w++) {
        const unsigned lo = rv[w] & 0xFFFFu;
        const unsigned hi = rv[w] >> 16;
        if (lo < tcmp) { c++; s += pat2f(lo); }
        if (hi < tcmp) { c++; s += pat2f(hi); }
        mnp = min(mnp, min(lo, hi));
    }
    c = __reduce_add_sync(0xFFFFFFFFu, c);
    mnp = __reduce_min_sync(0xFFFFFFFFu, mnp);
#pragma unroll
    for (int off = 16; off; off >>= 1)
        s += __shfl_down_sync(0xFFFFFFFFu, s, off);
    if (lane == 0) { wu[wid] = c; wf[wid] = s; hist[wid] = mnp; }
    __syncthreads();
    if (tid == 0) {
        unsigned ct = 0; float st = 0.0f; unsigned mt = 0x7C00u;
#pragma unroll
        for (int w = 0; w < 8; w++) { ct += wu[w]; st += wf[w]; mt = min(mt, hist[w]); }
        s_ctot = ct; s_sall = st; s_minp = mt;
    }
    __syncthreads();

    if (s_ctot <= KSEL) {
        if (tid == 0) rl[row] = (float)s_ctot * t - s_sall;
        return;
    }

    // ---- top-byte digit walk (atomic-free, integer) ----
    unsigned remk = KSEL;
    unsigned D = s_minp >> 8;
    for (;;) {
        unsigned cd = 0;
#pragma unroll
        for (int w = 0; w < 8; w++) {
            cd += (((rv[w] & 0xFFFFu) >> 8) == D);
            cd += ((rv[w] >> 24) == D);
        }
        cd = __reduce_add_sync(0xFFFFFFFFu, cd);
        if (lane == 0) wu[wid] = cd;
        __syncthreads();
        if (tid == 0) {
            unsigned ct = 0;
#pragma unroll
            for (int w = 0; w < 8; w++) ct += wu[w];
            s_cd = ct;
        }
        __syncthreads();
        const unsigned cdtot = s_cd;
        __syncthreads();
        if (cdtot >= remk) break;
        remk -= cdtot;
        D++;
    }

    // ---- single low-byte histogram pass ----
    hist[tid] = 0;
    __syncthreads();
#pragma unroll
    for (int w = 0; w < 8; w++) {
        const unsigned lo = rv[w] & 0xFFFFu;
        const unsigned hi = rv[w] >> 16;
        if ((lo >> 8) == D) atomicAdd(&hist[lo & 255u], 1u);
        if ((hi >> 8) == D) atomicAdd(&hist[hi & 255u], 1u);
    }
    __syncthreads();
    if (tid < 32) {
        unsigned loc[8]; unsigned lsum = 0;
#pragma unroll
        for (int j = 0; j < 8; j++) { loc[j] = hist[tid * 8 + j]; lsum += loc[j]; }
        unsigned incl = lsum;
#pragma unroll
        for (int off = 1; off < 32; off <<= 1) {
            unsigned y = __shfl_up_sync(0xFFFFFFFFu, incl, off);
            if (tid >= off) incl += y;
        }
        const unsigned excl = incl - lsum;
        if (excl < remk && incl >= remk) {
            unsigned cum = excl;
#pragma unroll
            for (int j = 0; j < 8; j++) {
                if (cum + loc[j] >= remk) {
                    s_theta = (D << 8) | (unsigned)(tid * 8 + j);
                    break;
                }
                cum += loc[j];
            }
        }
    }
    __syncthreads();
    const unsigned theta_pat = s_theta;
    const float theta = pat2f(theta_pat);

    // ---- final: sum/count strictly below theta ----
    unsigned cl = 0; float sl = 0.0f;
#pragma unroll
    for (int w = 0; w < 8; w++) {
        const unsigned lo = rv[w] & 0xFFFFu;
        const unsigned hi = rv[w] >> 16;
        if (lo < theta_pat) { cl++; sl += pat2f(lo); }
        if (hi < theta_pat) { cl++; sl += pat2f(hi); }
    }
    cl = __reduce_add_sync(0xFFFFFFFFu, cl);
#pragma unroll
    for (int off = 16; off; off >>= 1)
        sl += __shfl_down_sync(0xFFFFFFFFu, sl, off);
    if (lane == 0) { wu[wid] = cl; wf[wid] = sl; }
    __syncthreads();
    if (tid == 0) {
        unsigned ct = 0; float st = 0.0f;
#pragma unroll
        for (int w = 0; w < 8; w++) { ct += wu[w]; st += wf[w]; }
        rl[row] = (float)KSEL * t - st - (float)(KSEL - ct) * theta;
    }
}

// ---------------------------------------------------------------------------
__global__ void finalize_kernel(float* __restrict__ out) {
    __shared__ float sm[256];
    for (int which = 0; which < 2; which++) {
        float s = 0.0f;
        for (int i = threadIdx.x; i < BDIM; i += 256) s += g_rl[which * BDIM + i];
        sm[threadIdx.x] = s;
        __syncthreads();
        for (int off = 128; off; off >>= 1) {
            if (threadIdx.x < off) sm[threadIdx.x] += sm[threadIdx.x + off];
            __syncthreads();
        }
        if (threadIdx.x == 0) out[which] = sm[0] / ((float)BDIM * (float)KSEL);
        __syncthreads();
    }
}

// ---------------------------------------------------------------------------
extern "C" void kernel_launch(void* const* d_in, const int* in_sizes, int n_in,
                              void* d_out, int out_size) {
    const float* X = (const float*)d_in[0];
    const float* Y = (const float*)d_in[1];
    float* out = (float*)d_out;

    cudaFuncSetAttribute(gemm_mma_kernel, cudaFuncAttributeMaxDynamicSharedMemorySize,
                         GEMM_SMEM);

    norms_kernel<<<dim3(BDIM, 2), 256>>>(X, Y);
    gemm_mma_kernel<<<dim3(BDIM / BN, BDIM / BM), 256, GEMM_SMEM>>>();
    select_kernel<<<dim3(BDIM, 2), 256>>>();
    finalize_kernel<<<1, 256>>>(out);
}